// round 8
// baseline (speedup 1.0000x reference)
#include <cuda_runtime.h>
#include <math.h>

#define B 4
#define HW 48
#define PIX 2304        // 48*48
#define D 64
#define JH 46
#define C 2116          // 46*46
#define CP 48           // padded inner dim
#define NSPLIT 4
#define KSEG (PIX/NSPLIT)   // 576

// ---------------- scratch (device globals; per-batch reuse, ~115MB) ----------------
__device__ float d_bg[B*PIX*D];
__device__ float d_ng[B*PIX];
__device__ float d_nbg[B*PIX];
__device__ float d_wwd[B*PIX];
__device__ float d_k1d[B*C];
__device__ float d_G[PIX*PIX];            // gram, one batch (21.2MB)
__device__ float d_Hh[HW*HW*JH*HW];       // y-diag sum of G (20.3MB)
__device__ float d_CA[PIX*JH*CP];         // attention, PADDED rows [jy][48] (20.3MB)
__device__ float d_Pm[HW*HW*HW*CP];       // y-diag sum of CA, PADDED v->48 (21.2MB)
__device__ float d_CB[PIX*PIX];           // diag box sum of CA (21.2MB)
__device__ float d_aclp[NSPLIT][PIX*D];
__device__ float d_tanhT[4097];           // logit LUT: -50*tanh(t)-50, t in [-8,8]

// ---------------- f32x2 packed FMA ----------------
__device__ __forceinline__ void ffma2(unsigned long long& d,
                                      unsigned long long a,
                                      unsigned long long b) {
    asm("fma.rn.f32x2 %0, %1, %2, %3;" : "=l"(d) : "l"(a), "l"(b), "l"(d));
}
__device__ __forceinline__ unsigned long long pack2(float lo, float hi) {
    unsigned long long r;
    asm("mov.b64 %0, {%1, %2};" : "=l"(r) : "f"(lo), "f"(hi));
    return r;
}
__device__ __forceinline__ float pairsum(unsigned long long p) {
    float lo = __uint_as_float((unsigned)(p & 0xffffffffull));
    float hi = __uint_as_float((unsigned)(p >> 32));
    return lo + hi;
}

// ---------------- block reduction (256 threads, 8 warps) ----------------
__device__ __forceinline__ float blkSum(float v, volatile float* sh) {
    for (int o = 16; o; o >>= 1) v += __shfl_down_sync(0xffffffffu, v, o);
    int w = threadIdx.x >> 5;
    if ((threadIdx.x & 31) == 0) sh[w] = v;
    __syncthreads();
    if (threadIdx.x == 0) {
        float s = 0.f;
        for (int i = 0; i < 8; i++) s += sh[i];
        sh[0] = s;
    }
    __syncthreads();
    float r = sh[0];
    __syncthreads();
    return r;
}

// ---------------- K0: logit LUT ----------------
__global__ void table_kernel() {
    int i = blockIdx.x * 256 + threadIdx.x;
    if (i < 4097) {
        float t = -8.f + i * (1.f / 256.f);
        d_tanhT[i] = -50.f * tanhf(t) - 50.f;
    }
}

// ---------------- K1: bg + pixel norms (all batches) ----------------
__global__ void prep_kernel(const float* __restrict__ g_in,
                            const float* __restrict__ mask) {
    int pix = blockIdx.x * 4 + (threadIdx.x >> 6);
    int ch  = threadIdx.x & 63;
    float g = g_in[pix * D + ch];
    float m = mask[pix];
    float bgv = g * m;
    d_bg[pix * D + ch] = bgv;
    float ng = g * g, nb = bgv * bgv;
    for (int o = 16; o; o >>= 1) {
        ng += __shfl_down_sync(0xffffffffu, ng, o);
        nb += __shfl_down_sync(0xffffffffu, nb, o);
    }
    __shared__ float sng[8], snb[8];
    int w = threadIdx.x >> 5;
    if ((threadIdx.x & 31) == 0) { sng[w] = ng; snb[w] = nb; }
    __syncthreads();
    if (ch == 0) {
        d_ng[pix]  = sng[w] + sng[w + 1];
        d_nbg[pix] = snb[w] + snb[w + 1];
    }
}

// ---------------- K2: box sums (all batches) ----------------
__global__ void box_kernel() {
    int idx = blockIdx.x * blockDim.x + threadIdx.x;
    if (idx >= B * PIX) return;
    int b = idx / PIX, p = idx % PIX;
    int y = p / HW, x = p % HW;
    float s = 0.f;
    for (int dy = 0; dy < 3; dy++)
        for (int dx = 0; dx < 3; dx++) {
            int yy = y + dy - 1, xx = x + dx - 1;
            if ((unsigned)yy < (unsigned)HW && (unsigned)xx < (unsigned)HW)
                s += d_ng[b * PIX + yy * HW + xx];
        }
    d_wwd[idx] = s;
    if (y < JH && x < JH) {
        float s2 = 0.f;
        for (int dy = 0; dy < 3; dy++)
            for (int dx = 0; dx < 3; dx++)
                s2 += d_nbg[b * PIX + (y + dy) * HW + (x + dx)];
        d_k1d[b * C + y * JH + x] = s2;
    }
}

// ---------------- K3: G = g_in @ bg^T (one batch), f32x2 packed ----------------
__global__ void gemmG_kernel(const float* __restrict__ g_in, int b) {
    __shared__ __align__(16) float As[64 * 66];
    __shared__ __align__(16) float Bs[64 * 66];
    int pt = blockIdx.y * 64, qt = blockIdx.x * 64;
    const float* Ap = g_in + (size_t)b * PIX * D;
    const float* Bp = d_bg + (size_t)b * PIX * D;
    int tid = threadIdx.x;
    for (int i = tid; i < 4096; i += 256) {
        int r = i >> 6, c = i & 63;
        As[r * 66 + c] = Ap[(pt + r) * D + c];
        Bs[r * 66 + c] = Bp[(qt + r) * D + c];
    }
    __syncthreads();
    int ty = tid >> 4, tx = tid & 15;
    unsigned long long acc[4][4] = {};
#pragma unroll
    for (int kp = 0; kp < 32; kp++) {
        int k = kp * 2;
        unsigned long long a2[4], b2[4];
#pragma unroll
        for (int i = 0; i < 4; i++) {
            a2[i] = *(const unsigned long long*)&As[(ty + 16 * i) * 66 + k];
            b2[i] = *(const unsigned long long*)&Bs[(tx + 16 * i) * 66 + k];
        }
#pragma unroll
        for (int i = 0; i < 4; i++)
#pragma unroll
            for (int j = 0; j < 4; j++) ffma2(acc[i][j], a2[i], b2[j]);
    }
#pragma unroll
    for (int i = 0; i < 4; i++)
#pragma unroll
        for (int j = 0; j < 4; j++)
            d_G[(size_t)(pt + ty + 16 * i) * PIX + qt + tx + 16 * j] = pairsum(acc[i][j]);
}

// ---------------- K4: Hh[y][px][jy][qx] = sum_dy G[(y+dy-1,px)][(jy+dy)*48+qx], float4 ----------------
__global__ void hbuild_kernel() {
    const int n4 = HW * HW * JH * (HW / 4);   // 1,271,808
    int idx = blockIdx.x * blockDim.x + threadIdx.x;
    if (idx >= n4) return;
    int q4 = idx % 12; int t = idx / 12;
    int jy = t % JH;   t /= JH;
    int px = t % HW;   int y = t / HW;
    const float4* G4 = (const float4*)d_G;
    float4 s = make_float4(0.f, 0.f, 0.f, 0.f);
#pragma unroll
    for (int dy = 0; dy < 3; dy++) {
        int yy = y + dy - 1;
        if ((unsigned)yy < (unsigned)HW) {
            float4 g = G4[(size_t)(yy * HW + px) * (PIX / 4) + (jy + dy) * 12 + q4];
            s.x += g.x; s.y += g.y; s.z += g.z; s.w += g.w;
        }
    }
    ((float4*)d_Hh)[idx] = s;
}

// ---------------- K5: fused CS row + stats + LUT-tanh + softmax -> CA ----------------
__global__ void row_kernel(int b) {
    __shared__ float rowbuf[C];
    __shared__ float red[8];
    int p = blockIdx.x;
    int y = p / HW, x = p % HW;
    int tid = threadIdx.x;
    float wv = d_wwd[b * PIX + p];

    // pass 1: DS1 = k1d + wwd - 2*CS, accumulate sum
    float s = 0.f;
    for (int j = tid; j < C; j += 256) {
        int jy = j / JH, jx = j - jy * JH;
        float cs = 0.f;
#pragma unroll
        for (int dx = 0; dx < 3; dx++) {
            int xx = x + dx - 1;
            if ((unsigned)xx < (unsigned)HW)
                cs += d_Hh[((y * HW + xx) * JH + jy) * HW + (jx + dx)];
        }
        float ds = d_k1d[b * C + j] + wv - 2.f * cs;
        rowbuf[j] = ds;
        s += ds;
    }
    float mu = blkSum(s, red) * (1.f / (float)C);

    // pass 2: variance (two-pass for accuracy)
    float s2 = 0.f;
    for (int j = tid; j < C; j += 256) { float d = rowbuf[j] - mu; s2 += d * d; }
    float var = blkSum(s2, red) * (1.f / (float)C);
    float inv_sd = rsqrtf(var);

    // pass 3: logit via LUT (g = -50*tanh(t)-50, t in [-8,8], lerp), single exp.
    // Uniform -50 shift cancels in softmax; max true logit >= 0 so no overflow/underflow.
    float se = 0.f;
    for (int j = tid; j < C; j += 256) {
        float t = (rowbuf[j] - mu) * inv_sd;
        float fi = fmaf(t, 256.f, 2048.f);
        fi = fminf(fmaxf(fi, 0.f), 4095.f);
        int i = (int)fi;
        float fr = fi - (float)i;
        float Ta = d_tanhT[i], Tb = d_tanhT[i + 1];
        float e = __expf(fmaf(fr, Tb - Ta, Ta));
        rowbuf[j] = e;
        se += e;
    }
    float invZ = 1.f / blkSum(se, red);

    // pass 4: write CA (padded [jy][48] rows)
    for (int j = tid; j < C; j += 256) {
        int jy = j / JH, jx = j - jy * JH;
        d_CA[((size_t)p * JH + jy) * CP + jx] = rowbuf[j] * invZ;
    }
}

// ---------------- K6: Pm[y][x][u][v<48] = sum_dy CA[(y+1-dy,x)][(u-dy)][v], float4 ----------------
__global__ void pm_kernel() {
    const int n4 = HW * HW * HW * (CP / 4);   // 1,327,104
    int idx = blockIdx.x * blockDim.x + threadIdx.x;
    if (idx >= n4) return;
    int q4 = idx % 12; int t = idx / 12;
    int u = t % HW;    t /= HW;
    int x = t % HW;    int y = t / HW;
    const float4* CA4 = (const float4*)d_CA;
    float4 s = make_float4(0.f, 0.f, 0.f, 0.f);
#pragma unroll
    for (int dy = 0; dy < 3; dy++) {
        int yy = y + 1 - dy, uu = u - dy;
        if ((unsigned)yy < (unsigned)HW && (unsigned)uu < (unsigned)JH) {
            float4 g = CA4[((size_t)(yy * HW + x) * JH + uu) * (CP / 4) + q4];
            s.x += g.x; s.y += g.y; s.z += g.z; s.w += g.w;
        }
    }
    if (q4 == 11) { s.z = 0.f; s.w = 0.f; }   // v = 46,47 pad -> zero
    ((float4*)d_Pm)[idx] = s;
}

// ---------------- K7: CB[(y,x)][(u,v)] = sum_dx Pm[y][x+1-dx][u][v-dx], float4 ----------------
// Per dx, EXACTLY ONE shifted element per output lane (diagonal sum).
__global__ void cb_kernel() {
    const int n4 = PIX * PIX / 4;             // 1,327,104
    int idx = blockIdx.x * blockDim.x + threadIdx.x;
    if (idx >= n4) return;
    int q4 = idx % 12; int t = idx / 12;
    int u = t % HW;    t /= HW;
    int x = t % HW;    int y = t / HW;
    int v0 = q4 * 4;
    float4 o = make_float4(0.f, 0.f, 0.f, 0.f);
#pragma unroll
    for (int dx = 0; dx < 3; dx++) {
        int xx = x + 1 - dx;
        if ((unsigned)xx < (unsigned)HW) {
            int rowbase = ((y * HW + xx) * HW + u) * CP;
            float4 f = ((const float4*)d_Pm)[rowbase / 4 + q4];
            float sm1 = 0.f, sm2 = 0.f;
            if (v0 > 0) { sm1 = d_Pm[rowbase + v0 - 1]; sm2 = d_Pm[rowbase + v0 - 2]; }
            if (dx == 0) {
                o.x += f.x;  o.y += f.y;  o.z += f.z;  o.w += f.w;
            } else if (dx == 1) {
                o.x += sm1;  o.y += f.x;  o.z += f.y;  o.w += f.z;
            } else {
                o.x += sm2;  o.y += sm1;  o.z += f.x;  o.w += f.y;
            }
        }
    }
    ((float4*)d_CB)[((size_t)(y * HW + x) * 576) + u * 12 + q4] = o;
}

// ---------------- K8: acl partials = CB @ bg, f32x2 packed, NO transpose ----------------
__global__ void gemmCB_kernel(int b) {
    __shared__ __align__(16) float Acb[64 * 66];   // [m][k], pad 66 for 8B-aligned pairs
    __shared__ float Bcb[64 * 65];                 // [k][n], pad 65, conflict-free
    int ks = blockIdx.y;
    int mt = blockIdx.x * 64;
    const float* bgp = d_bg + (size_t)b * PIX * D;
    int tid = threadIdx.x;
    int ty = tid >> 4, tx = tid & 15;
    unsigned long long acc[4][4] = {};
    int kbase = ks * KSEG;
    for (int kt = 0; kt < KSEG; kt += 64) {
        int k0 = kbase + kt;
        for (int i = tid; i < 4096; i += 256) {
            int r = i >> 6, c = i & 63;
            Acb[r * 66 + c] = d_CB[(size_t)(mt + r) * PIX + k0 + c];
            Bcb[r * 65 + c] = bgp[(k0 + r) * D + c];
        }
        __syncthreads();
#pragma unroll
        for (int kp = 0; kp < 32; kp++) {
            int k = kp * 2;
            unsigned long long a2[4], b2[4];
#pragma unroll
            for (int i = 0; i < 4; i++)
                a2[i] = *(const unsigned long long*)&Acb[(ty + 16 * i) * 66 + k];
#pragma unroll
            for (int j = 0; j < 4; j++) {
                float blo = Bcb[k * 65 + tx + 16 * j];
                float bhi = Bcb[(k + 1) * 65 + tx + 16 * j];
                b2[j] = pack2(blo, bhi);
            }
#pragma unroll
            for (int i = 0; i < 4; i++)
#pragma unroll
                for (int j = 0; j < 4; j++) ffma2(acc[i][j], a2[i], b2[j]);
        }
        __syncthreads();
    }
    float* outp = d_aclp[ks];
#pragma unroll
    for (int i = 0; i < 4; i++)
#pragma unroll
        for (int j = 0; j < 4; j++)
            outp[(mt + ty + 16 * i) * D + tx + 16 * j] = pairsum(acc[i][j]);
}

// ---------------- K9: ACL + concat + W2 GEMM + ELU ----------------
__global__ void final_kernel(const float* __restrict__ g_in,
                             const float* __restrict__ mask,
                             const float* __restrict__ W2,
                             const float* __restrict__ b2,
                             float* __restrict__ out, int b) {
    __shared__ float w2s[128 * 64];
    __shared__ float cats[4][128];
    int tid = threadIdx.x;
    int g = tid >> 6, dch = tid & 63;
    int pl  = blockIdx.x * 4 + g;
    int pix = b * PIX + pl;
    for (int i = tid; i < 128 * 64; i += 256) w2s[i] = W2[i];

    float gv = g_in[pix * D + dch];
    float m  = mask[pix];
    float a  = 0.f;
#pragma unroll
    for (int s = 0; s < NSPLIT; s++) a += d_aclp[s][pl * D + dch];
    float ACL = d_bg[pix * D + dch] + a * (1.f / 9.f) * (1.f - m);
    cats[g][dch]      = gv;
    cats[g][64 + dch] = ACL;
    __syncthreads();

    float acc = b2[dch];
#pragma unroll 16
    for (int k = 0; k < 128; k++) acc += cats[g][k] * w2s[k * 64 + dch];
    out[pix * D + dch] = acc > 0.f ? acc : expm1f(acc);
}

// ---------------- launch ----------------
extern "C" void kernel_launch(void* const* d_in, const int* in_sizes, int n_in,
                              void* d_out, int out_size) {
    const float* g_in = (const float*)d_in[0];
    const float* mask = (const float*)d_in[1];
    const float* W2   = (const float*)d_in[2];
    const float* b2   = (const float*)d_in[3];
    float* out = (float*)d_out;

    table_kernel<<<17, 256>>>();
    prep_kernel<<<B * PIX / 4, 256>>>(g_in, mask);
    box_kernel<<<(B * PIX + 255) / 256, 256>>>();

    for (int b = 0; b < B; b++) {
        gemmG_kernel<<<dim3(PIX / 64, PIX / 64), 256>>>(g_in, b);
        hbuild_kernel<<<(HW * HW * JH * (HW / 4) + 255) / 256, 256>>>();
        row_kernel<<<PIX, 256>>>(b);
        pm_kernel<<<(HW * HW * HW * (CP / 4) + 255) / 256, 256>>>();
        cb_kernel<<<(PIX * PIX / 4 + 255) / 256, 256>>>();
        gemmCB_kernel<<<dim3(PIX / 64, NSPLIT), 256>>>(b);
        final_kernel<<<PIX / 4, 256>>>(g_in, mask, W2, b2, out, b);
    }
}

// round 11
// speedup vs baseline: 1.0567x; 1.0567x over previous
#include <cuda_runtime.h>
#include <math.h>

#define B 4
#define HW 48
#define PIX 2304        // 48*48
#define D 64
#define JH 46
#define C 2116          // 46*46
#define CP 48           // padded inner dim
#define NSPLIT 4
#define KSEG (PIX/NSPLIT)   // 576

// ---------------- scratch (device globals; per-batch reuse, ~115MB) ----------------
__device__ float d_bg[B*PIX*D];
__device__ float d_ng[B*PIX];
__device__ float d_nbg[B*PIX];
__device__ float d_wwd[B*PIX];
__device__ float d_k1d[B*C];
__device__ float d_G[PIX*PIX];            // gram, one batch (21.2MB)
__device__ float d_Hh[HW*HW*JH*HW];       // y-diag sum of G (20.3MB)
__device__ float d_CA[PIX*JH*CP];         // UNSCALED exp weights, padded rows (20.3MB)
__device__ float d_invZ[PIX];             // per-row softmax 1/Z
__device__ float d_Pm[HW*HW*HW*CP];       // y-diag sum of scaled CA (21.2MB)
__device__ float d_CB[PIX*PIX];           // diag box sum of CA (21.2MB)
__device__ float d_aclp[NSPLIT][PIX*D];
__device__ float d_tanhT[4097];           // logit LUT: -50*tanh(t)-50, t in [-8,8]

// ---------------- f32x2 packed FMA ----------------
__device__ __forceinline__ void ffma2(unsigned long long& d,
                                      unsigned long long a,
                                      unsigned long long b) {
    asm("fma.rn.f32x2 %0, %1, %2, %3;" : "=l"(d) : "l"(a), "l"(b), "l"(d));
}
__device__ __forceinline__ unsigned long long pack2(float lo, float hi) {
    unsigned long long r;
    asm("mov.b64 %0, {%1, %2};" : "=l"(r) : "f"(lo), "f"(hi));
    return r;
}
__device__ __forceinline__ float pairsum(unsigned long long p) {
    float lo = __uint_as_float((unsigned)(p & 0xffffffffull));
    float hi = __uint_as_float((unsigned)(p >> 32));
    return lo + hi;
}

// ---------------- block reduction (256 threads, 8 warps) ----------------
__device__ __forceinline__ float blkSum(float v, volatile float* sh) {
    for (int o = 16; o; o >>= 1) v += __shfl_down_sync(0xffffffffu, v, o);
    int w = threadIdx.x >> 5;
    if ((threadIdx.x & 31) == 0) sh[w] = v;
    __syncthreads();
    if (threadIdx.x == 0) {
        float s = 0.f;
        for (int i = 0; i < 8; i++) s += sh[i];
        sh[0] = s;
    }
    __syncthreads();
    float r = sh[0];
    __syncthreads();
    return r;
}

// ---------------- K0: logit LUT ----------------
__global__ void table_kernel() {
    int i = blockIdx.x * 256 + threadIdx.x;
    if (i < 4097) {
        float t = -8.f + i * (1.f / 256.f);
        d_tanhT[i] = -50.f * tanhf(t) - 50.f;
    }
}

// ---------------- K1: bg + pixel norms (all batches) ----------------
__global__ void prep_kernel(const float* __restrict__ g_in,
                            const float* __restrict__ mask) {
    int pix = blockIdx.x * 4 + (threadIdx.x >> 6);
    int ch  = threadIdx.x & 63;
    float g = g_in[pix * D + ch];
    float m = mask[pix];
    float bgv = g * m;
    d_bg[pix * D + ch] = bgv;
    float ng = g * g, nb = bgv * bgv;
    for (int o = 16; o; o >>= 1) {
        ng += __shfl_down_sync(0xffffffffu, ng, o);
        nb += __shfl_down_sync(0xffffffffu, nb, o);
    }
    __shared__ float sng[8], snb[8];
    int w = threadIdx.x >> 5;
    if ((threadIdx.x & 31) == 0) { sng[w] = ng; snb[w] = nb; }
    __syncthreads();
    if (ch == 0) {
        d_ng[pix]  = sng[w] + sng[w + 1];
        d_nbg[pix] = snb[w] + snb[w + 1];
    }
}

// ---------------- K2: box sums (all batches) ----------------
__global__ void box_kernel() {
    int idx = blockIdx.x * blockDim.x + threadIdx.x;
    if (idx >= B * PIX) return;
    int b = idx / PIX, p = idx % PIX;
    int y = p / HW, x = p % HW;
    float s = 0.f;
    for (int dy = 0; dy < 3; dy++)
        for (int dx = 0; dx < 3; dx++) {
            int yy = y + dy - 1, xx = x + dx - 1;
            if ((unsigned)yy < (unsigned)HW && (unsigned)xx < (unsigned)HW)
                s += d_ng[b * PIX + yy * HW + xx];
        }
    d_wwd[idx] = s;
    if (y < JH && x < JH) {
        float s2 = 0.f;
        for (int dy = 0; dy < 3; dy++)
            for (int dx = 0; dx < 3; dx++)
                s2 += d_nbg[b * PIX + (y + dy) * HW + (x + dx)];
        d_k1d[b * C + y * JH + x] = s2;
    }
}

// ---------------- K3: G via SYMMETRIC gram: G[p][q] = mask[q] * (g_in[p].g_in[q]) ----------------
// Only tiles pt<=qt computed; mirror written through smem staging.
__global__ void gemmG_kernel(const float* __restrict__ g_in,
                             const float* __restrict__ mask, int b) {
    int ptile = blockIdx.y, qtile = blockIdx.x;
    if (ptile > qtile) return;                 // lower-triangle blocks exit immediately
    __shared__ __align__(16) float As[64 * 66];
    __shared__ __align__(16) float Bs[64 * 66];
    __shared__ float mp[64], mq[64];
    int pt = ptile * 64, qt = qtile * 64;
    const float* Ap = g_in + (size_t)b * PIX * D;
    int tid = threadIdx.x;
    for (int i = tid; i < 4096; i += 256) {
        int r = i >> 6, c = i & 63;
        As[r * 66 + c] = Ap[(pt + r) * D + c];
        Bs[r * 66 + c] = Ap[(qt + r) * D + c];
    }
    if (tid < 64)       mp[tid]      = mask[b * PIX + pt + tid];
    else if (tid < 128) mq[tid - 64] = mask[b * PIX + qt + tid - 64];
    __syncthreads();
    int ty = tid >> 4, tx = tid & 15;
    unsigned long long acc[4][4] = {};
#pragma unroll
    for (int kp = 0; kp < 32; kp++) {
        int k = kp * 2;
        unsigned long long a2[4], b2[4];
#pragma unroll
        for (int i = 0; i < 4; i++) {
            a2[i] = *(const unsigned long long*)&As[(ty + 16 * i) * 66 + k];
            b2[i] = *(const unsigned long long*)&Bs[(tx + 16 * i) * 66 + k];
        }
#pragma unroll
        for (int i = 0; i < 4; i++)
#pragma unroll
            for (int j = 0; j < 4; j++) ffma2(acc[i][j], a2[i], b2[j]);
    }
    // direct write: G[pt+r][qt+c] = v * mask[qt+c]
    float v[4][4];
#pragma unroll
    for (int i = 0; i < 4; i++)
#pragma unroll
        for (int j = 0; j < 4; j++) {
            v[i][j] = pairsum(acc[i][j]);
            d_G[(size_t)(pt + ty + 16 * i) * PIX + qt + tx + 16 * j] =
                v[i][j] * mq[tx + 16 * j];
        }
    if (ptile == qtile) return;
    // mirror write via smem transpose: G[qt+c][pt+r] = v * mask[pt+r]
    __syncthreads();
#pragma unroll
    for (int i = 0; i < 4; i++)
#pragma unroll
        for (int j = 0; j < 4; j++)
            As[(tx + 16 * j) * 66 + (ty + 16 * i)] = v[i][j];
    __syncthreads();
    for (int i = 0; i < 16; i++) {
        int idx = i * 256 + tid;
        int c = idx >> 6, r = idx & 63;
        d_G[(size_t)(qt + c) * PIX + pt + r] = As[c * 66 + r] * mp[r];
    }
}

// ---------------- K4: Hh[y][px][jy][qx] = sum_dy G[(y+dy-1,px)][(jy+dy)*48+qx], float4 ----------------
__global__ void hbuild_kernel() {
    const int n4 = HW * HW * JH * (HW / 4);   // 1,271,808
    int idx = blockIdx.x * blockDim.x + threadIdx.x;
    if (idx >= n4) return;
    int q4 = idx % 12; int t = idx / 12;
    int jy = t % JH;   t /= JH;
    int px = t % HW;   int y = t / HW;
    const float4* G4 = (const float4*)d_G;
    float4 s = make_float4(0.f, 0.f, 0.f, 0.f);
#pragma unroll
    for (int dy = 0; dy < 3; dy++) {
        int yy = y + dy - 1;
        if ((unsigned)yy < (unsigned)HW) {
            float4 g = G4[(size_t)(yy * HW + px) * (PIX / 4) + (jy + dy) * 12 + q4];
            s.x += g.x; s.y += g.y; s.z += g.z; s.w += g.w;
        }
    }
    ((float4*)d_Hh)[idx] = s;
}

// ---------------- K5: fused CS row + single-pass stats + LUT softmax (2 passes) ----------------
__global__ void row_kernel(int b) {
    __shared__ float rowbuf[C];
    __shared__ float red[8];
    int p = blockIdx.x;
    int y = p / HW, x = p % HW;
    int tid = threadIdx.x;
    float wv = d_wwd[b * PIX + p];
    float k1d0 = d_k1d[b * C];     // constant shift sample -> z centered near 0

    // pass A: z = ds - (wv + k1d0) = (k1d[j]-k1d0) - 2*CS; accumulate sum & sumsq
    float s = 0.f, s2 = 0.f;
    for (int j = tid; j < C; j += 256) {
        int jy = j / JH, jx = j - jy * JH;
        float cs = 0.f;
#pragma unroll
        for (int dx = 0; dx < 3; dx++) {
            int xx = x + dx - 1;
            if ((unsigned)xx < (unsigned)HW)
                cs += d_Hh[((y * HW + xx) * JH + jy) * HW + (jx + dx)];
        }
        float z = (d_k1d[b * C + j] - k1d0) - 2.f * cs;
        rowbuf[j] = z;
        s += z;
        s2 = fmaf(z, z, s2);
    }
    float muz = blkSum(s, red) * (1.f / (float)C);
    float ez2 = blkSum(s2, red) * (1.f / (float)C);
    float var = fmaxf(ez2 - muz * muz, 1e-12f);
    float inv_sd = rsqrtf(var);

    // pass B: logit via LUT, exp, accumulate Z; write UNSCALED e to CA
    float se = 0.f;
    for (int j = tid; j < C; j += 256) {
        float t = (rowbuf[j] - muz) * inv_sd;
        float fi = fmaf(t, 256.f, 2048.f);
        fi = fminf(fmaxf(fi, 0.f), 4095.f);
        int i = (int)fi;
        float fr = fi - (float)i;
        float Ta = d_tanhT[i], Tb = d_tanhT[i + 1];
        float e = __expf(fmaf(fr, Tb - Ta, Ta));
        int jy = j / JH, jx = j - jy * JH;
        d_CA[((size_t)p * JH + jy) * CP + jx] = e;
        se += e;
    }
    float Z = blkSum(se, red);
    if (tid == 0) d_invZ[p] = 1.f / Z;
}

// ---------------- K6: Pm[y][x][u][v] = sum_dy invZ[row] * CA[(y+1-dy,x)][(u-dy)][v], float4 ----------------
__global__ void pm_kernel() {
    const int n4 = HW * HW * HW * (CP / 4);   // 1,327,104
    int idx = blockIdx.x * blockDim.x + threadIdx.x;
    if (idx >= n4) return;
    int q4 = idx % 12; int t = idx / 12;
    int u = t % HW;    t /= HW;
    int x = t % HW;    int y = t / HW;
    const float4* CA4 = (const float4*)d_CA;
    float4 s = make_float4(0.f, 0.f, 0.f, 0.f);
#pragma unroll
    for (int dy = 0; dy < 3; dy++) {
        int yy = y + 1 - dy, uu = u - dy;
        if ((unsigned)yy < (unsigned)HW && (unsigned)uu < (unsigned)JH) {
            int row = yy * HW + x;
            float iz = d_invZ[row];
            float4 g = CA4[((size_t)row * JH + uu) * (CP / 4) + q4];
            s.x = fmaf(g.x, iz, s.x); s.y = fmaf(g.y, iz, s.y);
            s.z = fmaf(g.z, iz, s.z); s.w = fmaf(g.w, iz, s.w);
        }
    }
    if (q4 == 11) { s.z = 0.f; s.w = 0.f; }   // v = 46,47 pad -> zero
    ((float4*)d_Pm)[idx] = s;
}

// ---------------- K7: CB[(y,x)][(u,v)] = sum_dx Pm[y][x+1-dx][u][v-dx], float4 ----------------
__global__ void cb_kernel() {
    const int n4 = PIX * PIX / 4;             // 1,327,104
    int idx = blockIdx.x * blockDim.x + threadIdx.x;
    if (idx >= n4) return;
    int q4 = idx % 12; int t = idx / 12;
    int u = t % HW;    t /= HW;
    int x = t % HW;    int y = t / HW;
    int v0 = q4 * 4;
    float4 o = make_float4(0.f, 0.f, 0.f, 0.f);
#pragma unroll
    for (int dx = 0; dx < 3; dx++) {
        int xx = x + 1 - dx;
        if ((unsigned)xx < (unsigned)HW) {
            int rowbase = ((y * HW + xx) * HW + u) * CP;
            float4 f = ((const float4*)d_Pm)[rowbase / 4 + q4];
            float sm1 = 0.f, sm2 = 0.f;
            if (v0 > 0) { sm1 = d_Pm[rowbase + v0 - 1]; sm2 = d_Pm[rowbase + v0 - 2]; }
            if (dx == 0) {
                o.x += f.x;  o.y += f.y;  o.z += f.z;  o.w += f.w;
            } else if (dx == 1) {
                o.x += sm1;  o.y += f.x;  o.z += f.y;  o.w += f.z;
            } else {
                o.x += sm2;  o.y += sm1;  o.z += f.x;  o.w += f.y;
            }
        }
    }
    ((float4*)d_CB)[((size_t)(y * HW + x) * 576) + u * 12 + q4] = o;
}

// ---------------- K8: acl partials = CB @ bg, f32x2 packed ----------------
__global__ void gemmCB_kernel(int b) {
    __shared__ __align__(16) float Acb[64 * 66];   // [m][k]
    __shared__ float Bcb[64 * 65];                 // [k][n]
    int ks = blockIdx.y;
    int mt = blockIdx.x * 64;
    const float* bgp = d_bg + (size_t)b * PIX * D;
    int tid = threadIdx.x;
    int ty = tid >> 4, tx = tid & 15;
    unsigned long long acc[4][4] = {};
    int kbase = ks * KSEG;
    for (int kt = 0; kt < KSEG; kt += 64) {
        int k0 = kbase + kt;
        for (int i = tid; i < 4096; i += 256) {
            int r = i >> 6, c = i & 63;
            Acb[r * 66 + c] = d_CB[(size_t)(mt + r) * PIX + k0 + c];
            Bcb[r * 65 + c] = bgp[(k0 + r) * D + c];
        }
        __syncthreads();
#pragma unroll
        for (int kp = 0; kp < 32; kp++) {
            int k = kp * 2;
            unsigned long long a2[4], b2[4];
#pragma unroll
            for (int i = 0; i < 4; i++)
                a2[i] = *(const unsigned long long*)&Acb[(ty + 16 * i) * 66 + k];
#pragma unroll
            for (int j = 0; j < 4; j++) {
                float blo = Bcb[k * 65 + tx + 16 * j];
                float bhi = Bcb[(k + 1) * 65 + tx + 16 * j];
                b2[j] = pack2(blo, bhi);
            }
#pragma unroll
            for (int i = 0; i < 4; i++)
#pragma unroll
                for (int j = 0; j < 4; j++) ffma2(acc[i][j], a2[i], b2[j]);
        }
        __syncthreads();
    }
    float* outp = d_aclp[ks];
#pragma unroll
    for (int i = 0; i < 4; i++)
#pragma unroll
        for (int j = 0; j < 4; j++)
            outp[(mt + ty + 16 * i) * D + tx + 16 * j] = pairsum(acc[i][j]);
}

// ---------------- K9: ACL + concat + W2 GEMM + ELU ----------------
__global__ void final_kernel(const float* __restrict__ g_in,
                             const float* __restrict__ mask,
                             const float* __restrict__ W2,
                             const float* __restrict__ b2,
                             float* __restrict__ out, int b) {
    __shared__ float w2s[128 * 64];
    __shared__ float cats[4][128];
    int tid = threadIdx.x;
    int g = tid >> 6, dch = tid & 63;
    int pl  = blockIdx.x * 4 + g;
    int pix = b * PIX + pl;
    for (int i = tid; i < 128 * 64; i += 256) w2s[i] = W2[i];

    float gv = g_in[pix * D + dch];
    float m  = mask[pix];
    float a  = 0.f;
#pragma unroll
    for (int s = 0; s < NSPLIT; s++) a += d_aclp[s][pl * D + dch];
    float ACL = d_bg[pix * D + dch] + a * (1.f / 9.f) * (1.f - m);
    cats[g][dch]      = gv;
    cats[g][64 + dch] = ACL;
    __syncthreads();

    float acc = b2[dch];
#pragma unroll 16
    for (int k = 0; k < 128; k++) acc += cats[g][k] * w2s[k * 64 + dch];
    out[pix * D + dch] = acc > 0.f ? acc : expm1f(acc);
}

// ---------------- launch ----------------
extern "C" void kernel_launch(void* const* d_in, const int* in_sizes, int n_in,
                              void* d_out, int out_size) {
    const float* g_in = (const float*)d_in[0];
    const float* mask = (const float*)d_in[1];
    const float* W2   = (const float*)d_in[2];
    const float* b2   = (const float*)d_in[3];
    float* out = (float*)d_out;

    table_kernel<<<17, 256>>>();
    prep_kernel<<<B * PIX / 4, 256>>>(g_in, mask);
    box_kernel<<<(B * PIX + 255) / 256, 256>>>();

    for (int b = 0; b < B; b++) {
        gemmG_kernel<<<dim3(PIX / 64, PIX / 64), 256>>>(g_in, mask, b);
        hbuild_kernel<<<(HW * HW * JH * (HW / 4) + 255) / 256, 256>>>();
        row_kernel<<<PIX, 256>>>(b);
        pm_kernel<<<(HW * HW * HW * (CP / 4) + 255) / 256, 256>>>();
        cb_kernel<<<(PIX * PIX / 4 + 255) / 256, 256>>>();
        gemmCB_kernel<<<dim3(PIX / 64, NSPLIT), 256>>>(b);
        final_kernel<<<PIX / 4, 256>>>(g_in, mask, W2, b2, out, b);
    }
}

// round 12
// speedup vs baseline: 1.5723x; 1.4879x over previous
#include <cuda_runtime.h>
#include <math.h>

#define B 4
#define HW 48
#define PIX 2304        // 48*48
#define D 64
#define JH 46
#define C 2116          // 46*46
#define CP 48           // padded inner dim
#define CROW (JH*CP)    // 2208, padded row length
#define NSPLIT 9
#define KSEG (PIX/NSPLIT)   // 256

// ---------------- scratch (device globals; per-batch reuse, ~113MB) ----------------
__device__ float d_bg[B*PIX*D];
__device__ float d_nbg[B*PIX];
__device__ float d_k1d[B*CROW];           // PADDED [jy][48] 3x3 valid box sum of nbg
__device__ float d_G[PIX*PIX];            // gram, one batch (21.2MB)
__device__ float d_Hh[HW*HW*JH*HW];       // y-diag sum of G (20.3MB)
__device__ float d_CA[PIX*CROW];          // UNSCALED exp weights, padded rows (20.3MB)
__device__ float d_invZ[PIX];             // per-row softmax 1/Z
__device__ float d_Pm[HW*HW*HW*CP];       // y-diag sum of scaled CA (21.2MB)
__device__ float d_CB[PIX*PIX];           // diag box sum of CA (21.2MB)
__device__ float d_aclp[NSPLIT][PIX*D];   // 5.3MB
__device__ float d_tanhT[4097];           // logit LUT: -50*tanh(t)-50, t in [-8,8]

// ---------------- f32x2 packed FMA ----------------
__device__ __forceinline__ void ffma2(unsigned long long& d,
                                      unsigned long long a,
                                      unsigned long long b) {
    asm("fma.rn.f32x2 %0, %1, %2, %3;" : "=l"(d) : "l"(a), "l"(b), "l"(d));
}
__device__ __forceinline__ unsigned long long pack2(float lo, float hi) {
    unsigned long long r;
    asm("mov.b64 %0, {%1, %2};" : "=l"(r) : "f"(lo), "f"(hi));
    return r;
}
__device__ __forceinline__ float pairsum(unsigned long long p) {
    float lo = __uint_as_float((unsigned)(p & 0xffffffffull));
    float hi = __uint_as_float((unsigned)(p >> 32));
    return lo + hi;
}

// ---------------- block reduction (256 threads, 8 warps) ----------------
__device__ __forceinline__ float blkSum(float v, volatile float* sh) {
    for (int o = 16; o; o >>= 1) v += __shfl_down_sync(0xffffffffu, v, o);
    int w = threadIdx.x >> 5;
    if ((threadIdx.x & 31) == 0) sh[w] = v;
    __syncthreads();
    if (threadIdx.x == 0) {
        float s = 0.f;
        for (int i = 0; i < 8; i++) s += sh[i];
        sh[0] = s;
    }
    __syncthreads();
    float r = sh[0];
    __syncthreads();
    return r;
}

// ---------------- K0: logit LUT ----------------
__global__ void table_kernel() {
    int i = blockIdx.x * 256 + threadIdx.x;
    if (i < 4097) {
        float t = -8.f + i * (1.f / 256.f);
        d_tanhT[i] = -50.f * tanhf(t) - 50.f;
    }
}

// ---------------- K1: bg + masked pixel norm (all batches) ----------------
__global__ void prep_kernel(const float* __restrict__ g_in,
                            const float* __restrict__ mask) {
    int pix = blockIdx.x * 4 + (threadIdx.x >> 6);
    int ch  = threadIdx.x & 63;
    float g = g_in[pix * D + ch];
    float m = mask[pix];
    float bgv = g * m;
    d_bg[pix * D + ch] = bgv;
    float nb = bgv * bgv;
    for (int o = 16; o; o >>= 1)
        nb += __shfl_down_sync(0xffffffffu, nb, o);
    __shared__ float snb[8];
    int w = threadIdx.x >> 5;
    if ((threadIdx.x & 31) == 0) snb[w] = nb;
    __syncthreads();
    if (ch == 0)
        d_nbg[pix] = snb[w] + snb[w + 1];
}

// ---------------- K2: k1d valid box sum, PADDED rows (all batches) ----------------
__global__ void box_kernel() {
    int idx = blockIdx.x * blockDim.x + threadIdx.x;
    if (idx >= B * C) return;
    int b = idx / C, j = idx % C;
    int jy = j / JH, jx = j % JH;
    float s2 = 0.f;
    for (int dy = 0; dy < 3; dy++)
        for (int dx = 0; dx < 3; dx++)
            s2 += d_nbg[b * PIX + (jy + dy) * HW + (jx + dx)];
    d_k1d[b * CROW + jy * CP + jx] = s2;    // pad lanes stay 0 (zero-init, never written)
}

// ---------------- K3: G via SYMMETRIC gram: G[p][q] = mask[q] * (g_in[p].g_in[q]) ----------------
__global__ void gemmG_kernel(const float* __restrict__ g_in,
                             const float* __restrict__ mask, int b) {
    int ptile = blockIdx.y, qtile = blockIdx.x;
    if (ptile > qtile) return;
    __shared__ __align__(16) float As[64 * 66];
    __shared__ __align__(16) float Bs[64 * 66];
    __shared__ float mp[64], mq[64];
    int pt = ptile * 64, qt = qtile * 64;
    const float* Ap = g_in + (size_t)b * PIX * D;
    int tid = threadIdx.x;
    for (int i = tid; i < 4096; i += 256) {
        int r = i >> 6, c = i & 63;
        As[r * 66 + c] = Ap[(pt + r) * D + c];
        Bs[r * 66 + c] = Ap[(qt + r) * D + c];
    }
    if (tid < 64)       mp[tid]      = mask[b * PIX + pt + tid];
    else if (tid < 128) mq[tid - 64] = mask[b * PIX + qt + tid - 64];
    __syncthreads();
    int ty = tid >> 4, tx = tid & 15;
    unsigned long long acc[4][4] = {};
#pragma unroll
    for (int kp = 0; kp < 32; kp++) {
        int k = kp * 2;
        unsigned long long a2[4], b2[4];
#pragma unroll
        for (int i = 0; i < 4; i++) {
            a2[i] = *(const unsigned long long*)&As[(ty + 16 * i) * 66 + k];
            b2[i] = *(const unsigned long long*)&Bs[(tx + 16 * i) * 66 + k];
        }
#pragma unroll
        for (int i = 0; i < 4; i++)
#pragma unroll
            for (int j = 0; j < 4; j++) ffma2(acc[i][j], a2[i], b2[j]);
    }
    float v[4][4];
#pragma unroll
    for (int i = 0; i < 4; i++)
#pragma unroll
        for (int j = 0; j < 4; j++) {
            v[i][j] = pairsum(acc[i][j]);
            d_G[(size_t)(pt + ty + 16 * i) * PIX + qt + tx + 16 * j] =
                v[i][j] * mq[tx + 16 * j];
        }
    if (ptile == qtile) return;
    __syncthreads();
#pragma unroll
    for (int i = 0; i < 4; i++)
#pragma unroll
        for (int j = 0; j < 4; j++)
            As[(tx + 16 * j) * 66 + (ty + 16 * i)] = v[i][j];
    __syncthreads();
    for (int i = 0; i < 16; i++) {
        int idx = i * 256 + tid;
        int c = idx >> 6, r = idx & 63;
        d_G[(size_t)(qt + c) * PIX + pt + r] = As[c * 66 + r] * mp[r];
    }
}

// ---------------- K4: Hh[y][px][jy][qx] = sum_dy G[(y+dy-1,px)][(jy+dy)*48+qx], float4 ----------------
__global__ void hbuild_kernel() {
    const int n4 = HW * HW * JH * (HW / 4);
    int idx = blockIdx.x * blockDim.x + threadIdx.x;
    if (idx >= n4) return;
    int q4 = idx % 12; int t = idx / 12;
    int jy = t % JH;   t /= JH;
    int px = t % HW;   int y = t / HW;
    const float4* G4 = (const float4*)d_G;
    float4 s = make_float4(0.f, 0.f, 0.f, 0.f);
#pragma unroll
    for (int dy = 0; dy < 3; dy++) {
        int yy = y + dy - 1;
        if ((unsigned)yy < (unsigned)HW) {
            float4 g = G4[(size_t)(yy * HW + px) * (PIX / 4) + (jy + dy) * 12 + q4];
            s.x += g.x; s.y += g.y; s.z += g.z; s.w += g.w;
        }
    }
    ((float4*)d_Hh)[idx] = s;
}

// ---------------- K5: fused CS row + stats + LUT softmax, FLOAT4 body ----------------
// Unit = (jy, q4): 4 jx lanes. cs[L] = P0[v0+L] + P1[v0+L+1] + P2[v0+L+2],
// planes Pd = Hh row (y, xx=x+dx-1), guarded. Pad lanes (q4=11, L=2,3) zeroed.
__global__ void row_kernel(int b) {
    __shared__ __align__(16) float rowbuf[CROW];
    __shared__ float red[8];
    int p = blockIdx.x;
    int y = p / HW, x = p % HW;
    int tid = threadIdx.x;
    const float* k1 = d_k1d + b * CROW;
    float k1d0 = k1[0];
    bool ok0 = (x - 1) >= 0, ok2 = (x + 1) < HW;
    const float* P0 = d_Hh + (size_t)(y * HW + (x - 1)) * JH * HW;
    const float* P1 = d_Hh + (size_t)(y * HW + x) * JH * HW;
    const float* P2 = d_Hh + (size_t)(y * HW + (x + 1)) * JH * HW;

    // pass A: z = (k1d - k1d0) - 2*cs, f4 units; accumulate sum & sumsq
    float s = 0.f, sq = 0.f;
    for (int u = tid; u < JH * 12; u += 256) {
        int jy = u / 12, q4 = u - jy * 12;
        int v0 = q4 * 4;
        int rb = jy * CP + v0;
        int c4 = jy * CP + ((v0 + 4 < 48) ? v0 + 4 : 47);
        int c5 = jy * CP + ((v0 + 5 < 48) ? v0 + 5 : 47);
        float4 cs = make_float4(0.f, 0.f, 0.f, 0.f);
        if (ok0) {
            float4 f0 = *(const float4*)(P0 + rb);
            cs.x += f0.x; cs.y += f0.y; cs.z += f0.z; cs.w += f0.w;
        }
        {
            float4 f1 = *(const float4*)(P1 + rb);
            float s1 = P1[c4];
            cs.x += f1.y; cs.y += f1.z; cs.z += f1.w; cs.w += s1;
        }
        if (ok2) {
            float4 f2 = *(const float4*)(P2 + rb);
            float sa = P2[c4], sb = P2[c5];
            cs.x += f2.z; cs.y += f2.w; cs.z += sa; cs.w += sb;
        }
        float4 k4 = *(const float4*)(k1 + rb);
        float4 z;
        z.x = (k4.x - k1d0) - 2.f * cs.x;
        z.y = (k4.y - k1d0) - 2.f * cs.y;
        z.z = (k4.z - k1d0) - 2.f * cs.z;
        z.w = (k4.w - k1d0) - 2.f * cs.w;
        if (q4 == 11) { z.z = 0.f; z.w = 0.f; }   // jx=46,47 pad -> neutral in sums
        *(float4*)(rowbuf + rb) = z;
        s += z.x + z.y + z.z + z.w;
        sq = fmaf(z.x, z.x, sq); sq = fmaf(z.y, z.y, sq);
        sq = fmaf(z.z, z.z, sq); sq = fmaf(z.w, z.w, sq);
    }
    float muz = blkSum(s, red) * (1.f / (float)C);
    float ez2 = blkSum(sq, red) * (1.f / (float)C);
    float var = fmaxf(ez2 - muz * muz, 1e-12f);
    float inv_sd = rsqrtf(var);

    // pass B: LUT logit + exp, f4 stores to CA; accumulate Z
    float se = 0.f;
    float* cap = d_CA + (size_t)p * CROW;
    for (int u = tid; u < JH * 12; u += 256) {
        int jy = u / 12, q4 = u - jy * 12;
        int rb = jy * CP + q4 * 4;
        float4 z4 = *(const float4*)(rowbuf + rb);
        float4 e4;
        float zl[4] = {z4.x, z4.y, z4.z, z4.w};
        float el[4];
#pragma unroll
        for (int L = 0; L < 4; L++) {
            float t = (zl[L] - muz) * inv_sd;
            float fi = fmaf(t, 256.f, 2048.f);
            fi = fminf(fmaxf(fi, 0.f), 4095.f);
            int i = (int)fi;
            float fr = fi - (float)i;
            float Ta = d_tanhT[i], Tb = d_tanhT[i + 1];
            el[L] = __expf(fmaf(fr, Tb - Ta, Ta));
        }
        e4.x = el[0]; e4.y = el[1]; e4.z = el[2]; e4.w = el[3];
        if (q4 == 11) { e4.z = 0.f; e4.w = 0.f; }  // exclude pad from Z
        se += e4.x + e4.y + e4.z + e4.w;
        *(float4*)(cap + rb) = e4;
    }
    float Z = blkSum(se, red);
    if (tid == 0) d_invZ[p] = 1.f / Z;
}

// ---------------- K6: Pm[y][x][u][v] = sum_dy invZ[row] * CA[(y+1-dy,x)][(u-dy)][v], float4 ----------------
__global__ void pm_kernel() {
    const int n4 = HW * HW * HW * (CP / 4);
    int idx = blockIdx.x * blockDim.x + threadIdx.x;
    if (idx >= n4) return;
    int q4 = idx % 12; int t = idx / 12;
    int u = t % HW;    t /= HW;
    int x = t % HW;    int y = t / HW;
    const float4* CA4 = (const float4*)d_CA;
    float4 s = make_float4(0.f, 0.f, 0.f, 0.f);
#pragma unroll
    for (int dy = 0; dy < 3; dy++) {
        int yy = y + 1 - dy, uu = u - dy;
        if ((unsigned)yy < (unsigned)HW && (unsigned)uu < (unsigned)JH) {
            int row = yy * HW + x;
            float iz = d_invZ[row];
            float4 g = CA4[(size_t)row * (CROW / 4) + uu * 12 + q4];
            s.x = fmaf(g.x, iz, s.x); s.y = fmaf(g.y, iz, s.y);
            s.z = fmaf(g.z, iz, s.z); s.w = fmaf(g.w, iz, s.w);
        }
    }
    if (q4 == 11) { s.z = 0.f; s.w = 0.f; }
    ((float4*)d_Pm)[idx] = s;
}

// ---------------- K7: CB[(y,x)][(u,v)] = sum_dx Pm[y][x+1-dx][u][v-dx], float4 ----------------
__global__ void cb_kernel() {
    const int n4 = PIX * PIX / 4;
    int idx = blockIdx.x * blockDim.x + threadIdx.x;
    if (idx >= n4) return;
    int q4 = idx % 12; int t = idx / 12;
    int u = t % HW;    t /= HW;
    int x = t % HW;    int y = t / HW;
    int v0 = q4 * 4;
    float4 o = make_float4(0.f, 0.f, 0.f, 0.f);
#pragma unroll
    for (int dx = 0; dx < 3; dx++) {
        int xx = x + 1 - dx;
        if ((unsigned)xx < (unsigned)HW) {
            int rowbase = ((y * HW + xx) * HW + u) * CP;
            float4 f = ((const float4*)d_Pm)[rowbase / 4 + q4];
            float sm1 = 0.f, sm2 = 0.f;
            if (v0 > 0) { sm1 = d_Pm[rowbase + v0 - 1]; sm2 = d_Pm[rowbase + v0 - 2]; }
            if (dx == 0) {
                o.x += f.x;  o.y += f.y;  o.z += f.z;  o.w += f.w;
            } else if (dx == 1) {
                o.x += sm1;  o.y += f.x;  o.z += f.y;  o.w += f.z;
            } else {
                o.x += sm2;  o.y += sm1;  o.z += f.x;  o.w += f.y;
            }
        }
    }
    ((float4*)d_CB)[((size_t)(y * HW + x) * 576) + u * 12 + q4] = o;
}

// ---------------- K8: acl partials = CB @ bg, f32x2 packed, NSPLIT=9 ----------------
__global__ void gemmCB_kernel(int b) {
    __shared__ __align__(16) float Acb[64 * 66];   // [m][k]
    __shared__ float Bcb[64 * 65];                 // [k][n]
    int ks = blockIdx.y;
    int mt = blockIdx.x * 64;
    const float* bgp = d_bg + (size_t)b * PIX * D;
    int tid = threadIdx.x;
    int ty = tid >> 4, tx = tid & 15;
    unsigned long long acc[4][4] = {};
    int kbase = ks * KSEG;
    for (int kt = 0; kt < KSEG; kt += 64) {
        int k0 = kbase + kt;
        for (int i = tid; i < 4096; i += 256) {
            int r = i >> 6, c = i & 63;
            Acb[r * 66 + c] = d_CB[(size_t)(mt + r) * PIX + k0 + c];
            Bcb[r * 65 + c] = bgp[(k0 + r) * D + c];
        }
        __syncthreads();
#pragma unroll
        for (int kp = 0; kp < 32; kp++) {
            int k = kp * 2;
            unsigned long long a2[4], b2[4];
#pragma unroll
            for (int i = 0; i < 4; i++)
                a2[i] = *(const unsigned long long*)&Acb[(ty + 16 * i) * 66 + k];
#pragma unroll
            for (int j = 0; j < 4; j++) {
                float blo = Bcb[k * 65 + tx + 16 * j];
                float bhi = Bcb[(k + 1) * 65 + tx + 16 * j];
                b2[j] = pack2(blo, bhi);
            }
#pragma unroll
            for (int i = 0; i < 4; i++)
#pragma unroll
                for (int j = 0; j < 4; j++) ffma2(acc[i][j], a2[i], b2[j]);
        }
        __syncthreads();
    }
    float* outp = d_aclp[ks];
#pragma unroll
    for (int i = 0; i < 4; i++)
#pragma unroll
        for (int j = 0; j < 4; j++)
            outp[(mt + ty + 16 * i) * D + tx + 16 * j] = pairsum(acc[i][j]);
}

// ---------------- K9: ACL + concat + W2 GEMM + ELU ----------------
__global__ void final_kernel(const float* __restrict__ g_in,
                             const float* __restrict__ mask,
                             const float* __restrict__ W2,
                             const float* __restrict__ b2,
                             float* __restrict__ out, int b) {
    __shared__ float w2s[128 * 64];
    __shared__ float cats[4][128];
    int tid = threadIdx.x;
    int g = tid >> 6, dch = tid & 63;
    int pl  = blockIdx.x * 4 + g;
    int pix = b * PIX + pl;
    for (int i = tid; i < 128 * 64; i += 256) w2s[i] = W2[i];

    float gv = g_in[pix * D + dch];
    float m  = mask[pix];
    float a  = 0.f;
#pragma unroll
    for (int s = 0; s < NSPLIT; s++) a += d_aclp[s][pl * D + dch];
    float ACL = d_bg[pix * D + dch] + a * (1.f / 9.f) * (1.f - m);
    cats[g][dch]      = gv;
    cats[g][64 + dch] = ACL;
    __syncthreads();

    float acc = b2[dch];
#pragma unroll 16
    for (int k = 0; k < 128; k++) acc += cats[g][k] * w2s[k * 64 + dch];
    out[pix * D + dch] = acc > 0.f ? acc : expm1f(acc);
}

// ---------------- launch ----------------
extern "C" void kernel_launch(void* const* d_in, const int* in_sizes, int n_in,
                              void* d_out, int out_size) {
    const float* g_in = (const float*)d_in[0];
    const float* mask = (const float*)d_in[1];
    const float* W2   = (const float*)d_in[2];
    const float* b2   = (const float*)d_in[3];
    float* out = (float*)d_out;

    table_kernel<<<17, 256>>>();
    prep_kernel<<<B * PIX / 4, 256>>>(g_in, mask);
    box_kernel<<<(B * C + 255) / 256, 256>>>();

    for (int b = 0; b < B; b++) {
        gemmG_kernel<<<dim3(PIX / 64, PIX / 64), 256>>>(g_in, mask, b);
        hbuild_kernel<<<(HW * HW * JH * (HW / 4) + 255) / 256, 256>>>();
        row_kernel<<<PIX, 256>>>(b);
        pm_kernel<<<(HW * HW * HW * (CP / 4) + 255) / 256, 256>>>();
        cb_kernel<<<(PIX * PIX / 4 + 255) / 256, 256>>>();
        gemmCB_kernel<<<dim3(PIX / 64, NSPLIT), 256>>>(b);
        final_kernel<<<PIX / 4, 256>>>(g_in, mask, W2, b2, out, b);
    }
}

// round 13
// speedup vs baseline: 1.8017x; 1.1459x over previous
#include <cuda_runtime.h>
#include <math.h>

#define B 4
#define HW 48
#define PIX 2304        // 48*48
#define D 64
#define JH 46
#define C 2116          // 46*46
#define CP 48           // padded inner dim
#define CROW (JH*CP)    // 2208, padded row length
#define NSPLIT 18
#define KSEG (PIX/NSPLIT)   // 128

// ---------------- scratch (device globals; per-batch reuse, ~118MB) ----------------
__device__ float d_bg[B*PIX*D];
__device__ float d_nbg[B*PIX];
__device__ float d_k1d[B*CROW];           // PADDED [jy][48] 3x3 valid box sum of nbg
__device__ float d_G[PIX*PIX];            // gram, one batch (21.2MB)
__device__ float d_Hh[HW*HW*JH*HW];       // y-diag sum of G (20.3MB)
__device__ float d_CA[PIX*CROW];          // UNSCALED exp weights, padded rows (20.3MB)
__device__ float d_invZ[PIX];             // per-row softmax 1/Z
__device__ float d_Pm[HW*HW*HW*CP];       // y-diag sum of scaled CA (21.2MB)
__device__ float d_CB[PIX*PIX];           // diag box sum of CA (21.2MB)
__device__ float d_aclp[NSPLIT][PIX*D];   // 10.6MB
__device__ float d_tanhT[4097];           // logit LUT: -50*tanh(t)-50, t in [-8,8]

// ---------------- f32x2 packed FMA ----------------
__device__ __forceinline__ void ffma2(unsigned long long& d,
                                      unsigned long long a,
                                      unsigned long long b) {
    asm("fma.rn.f32x2 %0, %1, %2, %3;" : "=l"(d) : "l"(a), "l"(b), "l"(d));
}
__device__ __forceinline__ unsigned long long pack2(float lo, float hi) {
    unsigned long long r;
    asm("mov.b64 %0, {%1, %2};" : "=l"(r) : "f"(lo), "f"(hi));
    return r;
}
__device__ __forceinline__ float pairsum(unsigned long long p) {
    float lo = __uint_as_float((unsigned)(p & 0xffffffffull));
    float hi = __uint_as_float((unsigned)(p >> 32));
    return lo + hi;
}

// ---------------- block reduction (256 threads, 8 warps) ----------------
__device__ __forceinline__ float blkSum(float v, volatile float* sh) {
    for (int o = 16; o; o >>= 1) v += __shfl_down_sync(0xffffffffu, v, o);
    int w = threadIdx.x >> 5;
    if ((threadIdx.x & 31) == 0) sh[w] = v;
    __syncthreads();
    if (threadIdx.x == 0) {
        float s = 0.f;
        for (int i = 0; i < 8; i++) s += sh[i];
        sh[0] = s;
    }
    __syncthreads();
    float r = sh[0];
    __syncthreads();
    return r;
}

// ---------------- K0: logit LUT ----------------
__global__ void table_kernel() {
    int i = blockIdx.x * 256 + threadIdx.x;
    if (i < 4097) {
        float t = -8.f + i * (1.f / 256.f);
        d_tanhT[i] = -50.f * tanhf(t) - 50.f;
    }
}

// ---------------- K1: bg + masked pixel norm (all batches) ----------------
__global__ void prep_kernel(const float* __restrict__ g_in,
                            const float* __restrict__ mask) {
    int pix = blockIdx.x * 4 + (threadIdx.x >> 6);
    int ch  = threadIdx.x & 63;
    float g = g_in[pix * D + ch];
    float m = mask[pix];
    float bgv = g * m;
    d_bg[pix * D + ch] = bgv;
    float nb = bgv * bgv;
    for (int o = 16; o; o >>= 1)
        nb += __shfl_down_sync(0xffffffffu, nb, o);
    __shared__ float snb[8];
    int w = threadIdx.x >> 5;
    if ((threadIdx.x & 31) == 0) snb[w] = nb;
    __syncthreads();
    if (ch == 0)
        d_nbg[pix] = snb[w] + snb[w + 1];
}

// ---------------- K2: k1d valid box sum, PADDED rows (all batches) ----------------
__global__ void box_kernel() {
    int idx = blockIdx.x * blockDim.x + threadIdx.x;
    if (idx >= B * C) return;
    int b = idx / C, j = idx % C;
    int jy = j / JH, jx = j % JH;
    float s2 = 0.f;
    for (int dy = 0; dy < 3; dy++)
        for (int dx = 0; dx < 3; dx++)
            s2 += d_nbg[b * PIX + (jy + dy) * HW + (jx + dx)];
    d_k1d[b * CROW + jy * CP + jx] = s2;    // pad lanes stay 0
}

// ---------------- K3: G[p][q] = mask[q] * (g_in[p].g_in[q]); 128x64 tile, 8x4 micro ----------------
// dynamic smem: As[128*66] + Bs[64*66] = 50688 B
__global__ void gemmG_kernel(const float* __restrict__ g_in,
                             const float* __restrict__ mask, int b) {
    extern __shared__ float sm[];
    float* As = sm;              // [row][k], stride 66
    float* Bs = sm + 128 * 66;   // [col][k], stride 66
    __shared__ float mq[64];
    int pt = blockIdx.y * 128, qt = blockIdx.x * 64;
    const float* Ap = g_in + (size_t)b * PIX * D;
    const unsigned long long* Ag = (const unsigned long long*)Ap;
    int tid = threadIdx.x;
    for (int i = tid; i < 128 * 32; i += 256) {
        int r = i >> 5, c2 = i & 31;
        *(unsigned long long*)&As[r * 66 + c2 * 2] = Ag[(size_t)(pt + r) * 32 + c2];
    }
    for (int i = tid; i < 64 * 32; i += 256) {
        int r = i >> 5, c2 = i & 31;
        *(unsigned long long*)&Bs[r * 66 + c2 * 2] = Ag[(size_t)(qt + r) * 32 + c2];
    }
    if (tid < 64) mq[tid] = mask[b * PIX + qt + tid];
    __syncthreads();
    int ty = tid >> 4, tx = tid & 15;
    unsigned long long acc[8][4] = {};
#pragma unroll 8
    for (int kp = 0; kp < 32; kp++) {
        int k = kp * 2;
        unsigned long long a2[8], b2[4];
#pragma unroll
        for (int i = 0; i < 8; i++)
            a2[i] = *(const unsigned long long*)&As[(ty + 16 * i) * 66 + k];
#pragma unroll
        for (int j = 0; j < 4; j++)
            b2[j] = *(const unsigned long long*)&Bs[(tx + 16 * j) * 66 + k];
#pragma unroll
        for (int i = 0; i < 8; i++)
#pragma unroll
            for (int j = 0; j < 4; j++) ffma2(acc[i][j], a2[i], b2[j]);
    }
#pragma unroll
    for (int i = 0; i < 8; i++)
#pragma unroll
        for (int j = 0; j < 4; j++)
            d_G[(size_t)(pt + ty + 16 * i) * PIX + qt + tx + 16 * j] =
                pairsum(acc[i][j]) * mq[tx + 16 * j];
}

// ---------------- K4: Hh[y][px][jy][qx] = sum_dy G[(y+dy-1,px)][(jy+dy)*48+qx], float4 ----------------
__global__ void hbuild_kernel() {
    const int n4 = HW * HW * JH * (HW / 4);
    int idx = blockIdx.x * blockDim.x + threadIdx.x;
    if (idx >= n4) return;
    int q4 = idx % 12; int t = idx / 12;
    int jy = t % JH;   t /= JH;
    int px = t % HW;   int y = t / HW;
    const float4* G4 = (const float4*)d_G;
    float4 s = make_float4(0.f, 0.f, 0.f, 0.f);
#pragma unroll
    for (int dy = 0; dy < 3; dy++) {
        int yy = y + dy - 1;
        if ((unsigned)yy < (unsigned)HW) {
            float4 g = G4[(size_t)(yy * HW + px) * (PIX / 4) + (jy + dy) * 12 + q4];
            s.x += g.x; s.y += g.y; s.z += g.z; s.w += g.w;
        }
    }
    ((float4*)d_Hh)[idx] = s;
}

// ---------------- K5: fused CS row + stats + LUT softmax; z kept in REGISTERS ----------------
__global__ void row_kernel(int b) {
    __shared__ float red[8];
    int p = blockIdx.x;
    int y = p / HW, x = p % HW;
    int tid = threadIdx.x;
    const float* k1 = d_k1d + b * CROW;
    float k1d0 = k1[0];
    bool ok0 = (x - 1) >= 0, ok2 = (x + 1) < HW;
    const float* P0 = d_Hh + (size_t)(y * HW + (x - 1)) * JH * HW;
    const float* P1 = d_Hh + (size_t)(y * HW + x) * JH * HW;
    const float* P2 = d_Hh + (size_t)(y * HW + (x + 1)) * JH * HW;

    // pass A: z = (k1d - k1d0) - 2*cs; z stays in registers (3 f4 units/thread)
    float4 zreg[3];
    float s = 0.f, sq = 0.f;
#pragma unroll
    for (int it = 0; it < 3; it++) {
        int u = tid + it * 256;
        if (u >= JH * 12) break;
        int jy = u / 12, q4 = u - jy * 12;
        int v0 = q4 * 4;
        int rb = jy * CP + v0;
        int c4 = jy * CP + ((v0 + 4 < 48) ? v0 + 4 : 47);
        int c5 = jy * CP + ((v0 + 5 < 48) ? v0 + 5 : 47);
        float4 cs = make_float4(0.f, 0.f, 0.f, 0.f);
        if (ok0) {
            float4 f0 = *(const float4*)(P0 + rb);
            cs.x += f0.x; cs.y += f0.y; cs.z += f0.z; cs.w += f0.w;
        }
        {
            float4 f1 = *(const float4*)(P1 + rb);
            float s1 = P1[c4];
            cs.x += f1.y; cs.y += f1.z; cs.z += f1.w; cs.w += s1;
        }
        if (ok2) {
            float4 f2 = *(const float4*)(P2 + rb);
            float sa = P2[c4], sb = P2[c5];
            cs.x += f2.z; cs.y += f2.w; cs.z += sa; cs.w += sb;
        }
        float4 k4 = *(const float4*)(k1 + rb);
        float4 z;
        z.x = (k4.x - k1d0) - 2.f * cs.x;
        z.y = (k4.y - k1d0) - 2.f * cs.y;
        z.z = (k4.z - k1d0) - 2.f * cs.z;
        z.w = (k4.w - k1d0) - 2.f * cs.w;
        if (q4 == 11) { z.z = 0.f; z.w = 0.f; }   // jx=46,47 pad -> neutral
        zreg[it] = z;
        s += z.x + z.y + z.z + z.w;
        sq = fmaf(z.x, z.x, sq); sq = fmaf(z.y, z.y, sq);
        sq = fmaf(z.z, z.z, sq); sq = fmaf(z.w, z.w, sq);
    }
    float muz = blkSum(s, red) * (1.f / (float)C);
    float ez2 = blkSum(sq, red) * (1.f / (float)C);
    float var = fmaxf(ez2 - muz * muz, 1e-12f);
    float inv_sd = rsqrtf(var);

    // pass B: LUT logit + exp from registers, f4 stores to CA; accumulate Z
    float se = 0.f;
    float* cap = d_CA + (size_t)p * CROW;
#pragma unroll
    for (int it = 0; it < 3; it++) {
        int u = tid + it * 256;
        if (u >= JH * 12) break;
        int jy = u / 12, q4 = u - jy * 12;
        int rb = jy * CP + q4 * 4;
        float4 z4 = zreg[it];
        float zl[4] = {z4.x, z4.y, z4.z, z4.w};
        float el[4];
#pragma unroll
        for (int L = 0; L < 4; L++) {
            float t = (zl[L] - muz) * inv_sd;
            float fi = fmaf(t, 256.f, 2048.f);
            fi = fminf(fmaxf(fi, 0.f), 4095.f);
            int i = (int)fi;
            float fr = fi - (float)i;
            float Ta = d_tanhT[i], Tb = d_tanhT[i + 1];
            el[L] = __expf(fmaf(fr, Tb - Ta, Ta));
        }
        float4 e4 = make_float4(el[0], el[1], el[2], el[3]);
        if (q4 == 11) { e4.z = 0.f; e4.w = 0.f; }
        se += e4.x + e4.y + e4.z + e4.w;
        *(float4*)(cap + rb) = e4;
    }
    float Z = blkSum(se, red);
    if (tid == 0) d_invZ[p] = 1.f / Z;
}

// ---------------- K6: Pm[y][x][u][v] = sum_dy invZ[row] * CA[(y+1-dy,x)][(u-dy)][v], float4 ----------------
__global__ void pm_kernel() {
    const int n4 = HW * HW * HW * (CP / 4);
    int idx = blockIdx.x * blockDim.x + threadIdx.x;
    if (idx >= n4) return;
    int q4 = idx % 12; int t = idx / 12;
    int u = t % HW;    t /= HW;
    int x = t % HW;    int y = t / HW;
    const float4* CA4 = (const float4*)d_CA;
    float4 s = make_float4(0.f, 0.f, 0.f, 0.f);
#pragma unroll
    for (int dy = 0; dy < 3; dy++) {
        int yy = y + 1 - dy, uu = u - dy;
        if ((unsigned)yy < (unsigned)HW && (unsigned)uu < (unsigned)JH) {
            int row = yy * HW + x;
            float iz = d_invZ[row];
            float4 g = CA4[(size_t)row * (CROW / 4) + uu * 12 + q4];
            s.x = fmaf(g.x, iz, s.x); s.y = fmaf(g.y, iz, s.y);
            s.z = fmaf(g.z, iz, s.z); s.w = fmaf(g.w, iz, s.w);
        }
    }
    if (q4 == 11) { s.z = 0.f; s.w = 0.f; }
    ((float4*)d_Pm)[idx] = s;
}

// ---------------- K7: CB[(y,x)][(u,v)] = sum_dx Pm[y][x+1-dx][u][v-dx], float4 ----------------
__global__ void cb_kernel() {
    const int n4 = PIX * PIX / 4;
    int idx = blockIdx.x * blockDim.x + threadIdx.x;
    if (idx >= n4) return;
    int q4 = idx % 12; int t = idx / 12;
    int u = t % HW;    t /= HW;
    int x = t % HW;    int y = t / HW;
    int v0 = q4 * 4;
    float4 o = make_float4(0.f, 0.f, 0.f, 0.f);
#pragma unroll
    for (int dx = 0; dx < 3; dx++) {
        int xx = x + 1 - dx;
        if ((unsigned)xx < (unsigned)HW) {
            int rowbase = ((y * HW + xx) * HW + u) * CP;
            float4 f = ((const float4*)d_Pm)[rowbase / 4 + q4];
            float sm1 = 0.f, sm2 = 0.f;
            if (v0 > 0) { sm1 = d_Pm[rowbase + v0 - 1]; sm2 = d_Pm[rowbase + v0 - 2]; }
            if (dx == 0) {
                o.x += f.x;  o.y += f.y;  o.z += f.z;  o.w += f.w;
            } else if (dx == 1) {
                o.x += sm1;  o.y += f.x;  o.z += f.y;  o.w += f.z;
            } else {
                o.x += sm2;  o.y += sm1;  o.z += f.x;  o.w += f.y;
            }
        }
    }
    ((float4*)d_CB)[((size_t)(y * HW + x) * 576) + u * 12 + q4] = o;
}

// ---------------- K8: acl partials = CB @ bg; 128-row tile, 8x4 micro, packed-B smem ----------------
// dynamic smem: As[128*66] (33792B) + Bpair[32*64] ull (16384B) = 50176 B
__global__ void gemmCB_kernel(int b) {
    extern __shared__ float sm[];
    float* Acb = sm;                                        // [m][k], stride 66
    unsigned long long* Bp = (unsigned long long*)(sm + 128 * 66);  // [kp][n]
    int ks = blockIdx.y;
    int mt = blockIdx.x * 128;
    const float* bgp = d_bg + (size_t)b * PIX * D;
    int tid = threadIdx.x;
    int ty = tid >> 4, tx = tid & 15;
    unsigned long long acc[8][4] = {};
    int kbase = ks * KSEG;
    for (int kt = 0; kt < KSEG; kt += 64) {
        int k0 = kbase + kt;
        for (int i = tid; i < 128 * 32; i += 256) {
            int r = i >> 5, c2 = i & 31;
            *(unsigned long long*)&Acb[r * 66 + c2 * 2] =
                *(const unsigned long long*)&d_CB[(size_t)(mt + r) * PIX + k0 + c2 * 2];
        }
        for (int i = tid; i < 32 * 64; i += 256) {
            int kp = i >> 6, n = i & 63;
            Bp[kp * 64 + n] = pack2(bgp[(k0 + 2 * kp) * D + n],
                                    bgp[(k0 + 2 * kp + 1) * D + n]);
        }
        __syncthreads();
#pragma unroll 8
        for (int kp = 0; kp < 32; kp++) {
            int k = kp * 2;
            unsigned long long a2[8], b2[4];
#pragma unroll
            for (int i = 0; i < 8; i++)
                a2[i] = *(const unsigned long long*)&Acb[(ty + 16 * i) * 66 + k];
#pragma unroll
            for (int j = 0; j < 4; j++)
                b2[j] = Bp[kp * 64 + tx + 16 * j];
#pragma unroll
            for (int i = 0; i < 8; i++)
#pragma unroll
                for (int j = 0; j < 4; j++) ffma2(acc[i][j], a2[i], b2[j]);
        }
        __syncthreads();
    }
    float* outp = d_aclp[ks];
#pragma unroll
    for (int i = 0; i < 8; i++)
#pragma unroll
        for (int j = 0; j < 4; j++)
            outp[(mt + ty + 16 * i) * D + tx + 16 * j] = pairsum(acc[i][j]);
}

// ---------------- K9: ACL + concat + W2 GEMM + ELU ----------------
__global__ void final_kernel(const float* __restrict__ g_in,
                             const float* __restrict__ mask,
                             const float* __restrict__ W2,
                             const float* __restrict__ b2,
                             float* __restrict__ out, int b) {
    __shared__ float w2s[128 * 64];
    __shared__ float cats[4][128];
    int tid = threadIdx.x;
    int g = tid >> 6, dch = tid & 63;
    int pl  = blockIdx.x * 4 + g;
    int pix = b * PIX + pl;
    for (int i = tid; i < 128 * 64; i += 256) w2s[i] = W2[i];

    float gv = g_in[pix * D + dch];
    float m  = mask[pix];
    float a  = 0.f;
#pragma unroll
    for (int s = 0; s < NSPLIT; s++) a += d_aclp[s][pl * D + dch];
    float ACL = d_bg[pix * D + dch] + a * (1.f / 9.f) * (1.f - m);
    cats[g][dch]      = gv;
    cats[g][64 + dch] = ACL;
    __syncthreads();

    float acc = b2[dch];
#pragma unroll 16
    for (int k = 0; k < 128; k++) acc += cats[g][k] * w2s[k * 64 + dch];
    out[pix * D + dch] = acc > 0.f ? acc : expm1f(acc);
}

// ---------------- launch ----------------
extern "C" void kernel_launch(void* const* d_in, const int* in_sizes, int n_in,
                              void* d_out, int out_size) {
    const float* g_in = (const float*)d_in[0];
    const float* mask = (const float*)d_in[1];
    const float* W2   = (const float*)d_in[2];
    const float* b2   = (const float*)d_in[3];
    float* out = (float*)d_out;

    cudaFuncSetAttribute(gemmG_kernel,
                         cudaFuncAttributeMaxDynamicSharedMemorySize, 50688);
    cudaFuncSetAttribute(gemmCB_kernel,
                         cudaFuncAttributeMaxDynamicSharedMemorySize, 50176);

    table_kernel<<<17, 256>>>();
    prep_kernel<<<B * PIX / 4, 256>>>(g_in, mask);
    box_kernel<<<(B * C + 255) / 256, 256>>>();

    for (int b = 0; b < B; b++) {
        gemmG_kernel<<<dim3(PIX / 64, PIX / 128), 256, 50688>>>(g_in, mask, b);
        hbuild_kernel<<<(HW * HW * JH * (HW / 4) + 255) / 256, 256>>>();
        row_kernel<<<PIX, 256>>>(b);
        pm_kernel<<<(HW * HW * HW * (CP / 4) + 255) / 256, 256>>>();
        cb_kernel<<<(PIX * PIX / 4 + 255) / 256, 256>>>();
        gemmCB_kernel<<<dim3(PIX / 128, NSPLIT), 256, 50176>>>(b);
        final_kernel<<<PIX / 4, 256>>>(g_in, mask, W2, b2, out, b);
    }
}

// round 15
// speedup vs baseline: 1.8930x; 1.0507x over previous
#include <cuda_runtime.h>
#include <math.h>

#define B 4
#define HW 48
#define PIX 2304        // 48*48
#define D 64
#define JH 46
#define C 2116          // 46*46
#define CP 48           // padded inner dim
#define CROW (JH*CP)    // 2208, padded row length
#define NSPLIT 18
#define KSEG (PIX/NSPLIT)   // 128

// ---------------- scratch (device globals; per-batch reuse, ~118MB) ----------------
__device__ float d_bg[B*PIX*D];
__device__ float d_nbg[B*PIX];
__device__ float d_k1d[B*CROW];           // PADDED [jy][48] 3x3 valid box sum of nbg
__device__ float d_G[PIX*PIX];            // gram, one batch (21.2MB)
__device__ float d_Hh[HW*HW*JH*HW];       // y-diag sum of G (20.3MB)
__device__ float d_CA[PIX*CROW];          // UNSCALED exp weights, padded rows (20.3MB)
__device__ float d_invZ[PIX];             // per-row softmax 1/Z
__device__ float d_Pm[HW*HW*HW*CP];       // y-diag sum of scaled CA (21.2MB)
__device__ float d_CB[PIX*PIX];           // diag box sum of CA (21.2MB)
__device__ float d_aclp[NSPLIT][PIX*D];   // 10.6MB
__device__ float d_tanhT[4097];           // logit LUT: -50*tanh(t)-50, t in [-8,8]

// ---------------- f32x2 packed FMA ----------------
__device__ __forceinline__ void ffma2(unsigned long long& d,
                                      unsigned long long a,
                                      unsigned long long b) {
    asm("fma.rn.f32x2 %0, %1, %2, %3;" : "=l"(d) : "l"(a), "l"(b), "l"(d));
}
__device__ __forceinline__ unsigned long long pack2(float lo, float hi) {
    unsigned long long r;
    asm("mov.b64 %0, {%1, %2};" : "=l"(r) : "f"(lo), "f"(hi));
    return r;
}
__device__ __forceinline__ float pairsum(unsigned long long p) {
    float lo = __uint_as_float((unsigned)(p & 0xffffffffull));
    float hi = __uint_as_float((unsigned)(p >> 32));
    return lo + hi;
}

// ---------------- block reductions ----------------
// 18 warps (576 threads)
__device__ __forceinline__ float blkSum18(float v, volatile float* sh) {
    for (int o = 16; o; o >>= 1) v += __shfl_down_sync(0xffffffffu, v, o);
    int w = threadIdx.x >> 5;
    if ((threadIdx.x & 31) == 0) sh[w] = v;
    __syncthreads();
    if (threadIdx.x == 0) {
        float s = 0.f;
        for (int i = 0; i < 18; i++) s += sh[i];
        sh[0] = s;
    }
    __syncthreads();
    float r = sh[0];
    __syncthreads();
    return r;
}

// ---------------- K0: logit LUT ----------------
__global__ void table_kernel() {
    int i = blockIdx.x * 256 + threadIdx.x;
    if (i < 4097) {
        float t = -8.f + i * (1.f / 256.f);
        d_tanhT[i] = -50.f * tanhf(t) - 50.f;
    }
}

// ---------------- K1: bg + masked pixel norm (all batches) ----------------
__global__ void prep_kernel(const float* __restrict__ g_in,
                            const float* __restrict__ mask) {
    int pix = blockIdx.x * 4 + (threadIdx.x >> 6);
    int ch  = threadIdx.x & 63;
    float g = g_in[pix * D + ch];
    float m = mask[pix];
    float bgv = g * m;
    d_bg[pix * D + ch] = bgv;
    float nb = bgv * bgv;
    for (int o = 16; o; o >>= 1)
        nb += __shfl_down_sync(0xffffffffu, nb, o);
    __shared__ float snb[8];
    int w = threadIdx.x >> 5;
    if ((threadIdx.x & 31) == 0) snb[w] = nb;
    __syncthreads();
    if (ch == 0)
        d_nbg[pix] = snb[w] + snb[w + 1];
}

// ---------------- K2: k1d valid box sum, PADDED rows (all batches) ----------------
__global__ void box_kernel() {
    int idx = blockIdx.x * blockDim.x + threadIdx.x;
    if (idx >= B * C) return;
    int b = idx / C, j = idx % C;
    int jy = j / JH, jx = j % JH;
    float s2 = 0.f;
    for (int dy = 0; dy < 3; dy++)
        for (int dx = 0; dx < 3; dx++)
            s2 += d_nbg[b * PIX + (jy + dy) * HW + (jx + dx)];
    d_k1d[b * CROW + jy * CP + jx] = s2;    // pad lanes stay 0
}

// ---------------- K3: G via SYMMETRIC gram, triangular 64x64 (measured 22.9us) ----------------
__global__ void gemmG_kernel(const float* __restrict__ g_in,
                             const float* __restrict__ mask, int b) {
    int ptile = blockIdx.y, qtile = blockIdx.x;
    if (ptile > qtile) return;
    __shared__ __align__(16) float As[64 * 66];
    __shared__ __align__(16) float Bs[64 * 66];
    __shared__ float mp[64], mq[64];
    int pt = ptile * 64, qt = qtile * 64;
    const float* Ap = g_in + (size_t)b * PIX * D;
    int tid = threadIdx.x;
    for (int i = tid; i < 4096; i += 256) {
        int r = i >> 6, c = i & 63;
        As[r * 66 + c] = Ap[(pt + r) * D + c];
        Bs[r * 66 + c] = Ap[(qt + r) * D + c];
    }
    if (tid < 64)       mp[tid]      = mask[b * PIX + pt + tid];
    else if (tid < 128) mq[tid - 64] = mask[b * PIX + qt + tid - 64];
    __syncthreads();
    int ty = tid >> 4, tx = tid & 15;
    unsigned long long acc[4][4] = {};
#pragma unroll
    for (int kp = 0; kp < 32; kp++) {
        int k = kp * 2;
        unsigned long long a2[4], b2[4];
#pragma unroll
        for (int i = 0; i < 4; i++) {
            a2[i] = *(const unsigned long long*)&As[(ty + 16 * i) * 66 + k];
            b2[i] = *(const unsigned long long*)&Bs[(tx + 16 * i) * 66 + k];
        }
#pragma unroll
        for (int i = 0; i < 4; i++)
#pragma unroll
            for (int j = 0; j < 4; j++) ffma2(acc[i][j], a2[i], b2[j]);
    }
    float v[4][4];
#pragma unroll
    for (int i = 0; i < 4; i++)
#pragma unroll
        for (int j = 0; j < 4; j++) {
            v[i][j] = pairsum(acc[i][j]);
            d_G[(size_t)(pt + ty + 16 * i) * PIX + qt + tx + 16 * j] =
                v[i][j] * mq[tx + 16 * j];
        }
    if (ptile == qtile) return;
    __syncthreads();
#pragma unroll
    for (int i = 0; i < 4; i++)
#pragma unroll
        for (int j = 0; j < 4; j++)
            As[(tx + 16 * j) * 66 + (ty + 16 * i)] = v[i][j];
    __syncthreads();
    for (int i = 0; i < 16; i++) {
        int idx = i * 256 + tid;
        int c = idx >> 6, r = idx & 63;
        d_G[(size_t)(qt + c) * PIX + pt + r] = As[c * 66 + r] * mp[r];
    }
}

// ---------------- K4: Hh[y][px][jy][qx] = sum_dy G[(y+dy-1,px)][(jy+dy)*48+qx], float4 ----------------
__global__ void hbuild_kernel() {
    const int n4 = HW * HW * JH * (HW / 4);
    int idx = blockIdx.x * blockDim.x + threadIdx.x;
    if (idx >= n4) return;
    int q4 = idx % 12; int t = idx / 12;
    int jy = t % JH;   t /= JH;
    int px = t % HW;   int y = t / HW;
    const float4* G4 = (const float4*)d_G;
    float4 s = make_float4(0.f, 0.f, 0.f, 0.f);
#pragma unroll
    for (int dy = 0; dy < 3; dy++) {
        int yy = y + dy - 1;
        if ((unsigned)yy < (unsigned)HW) {
            float4 g = G4[(size_t)(yy * HW + px) * (PIX / 4) + (jy + dy) * 12 + q4];
            s.x += g.x; s.y += g.y; s.z += g.z; s.w += g.w;
        }
    }
    ((float4*)d_Hh)[idx] = s;
}

// ---------------- K5: fused CS row + stats + LUT softmax; 576 thr, ONE f4 unit/thread ----------------
__global__ void row_kernel(int b) {
    __shared__ float red[18];
    int p = blockIdx.x;
    int y = p / HW, x = p % HW;
    int tid = threadIdx.x;
    const float* k1 = d_k1d + b * CROW;
    float k1d0 = k1[0];
    bool ok0 = (x - 1) >= 0, ok2 = (x + 1) < HW;
    const float* P0 = d_Hh + (size_t)(y * HW + (x - 1)) * JH * HW;
    const float* P1 = d_Hh + (size_t)(y * HW + x) * JH * HW;
    const float* P2 = d_Hh + (size_t)(y * HW + (x + 1)) * JH * HW;

    bool active = tid < JH * 12;   // 552 units
    int jy = tid / 12, q4 = tid - jy * 12;
    int v0 = q4 * 4;
    int rb = jy * CP + v0;
    float4 z = make_float4(0.f, 0.f, 0.f, 0.f);
    if (active) {
        int c4 = jy * CP + ((v0 + 4 < 48) ? v0 + 4 : 47);
        int c5 = jy * CP + ((v0 + 5 < 48) ? v0 + 5 : 47);
        float4 cs = make_float4(0.f, 0.f, 0.f, 0.f);
        if (ok0) {
            float4 f0 = *(const float4*)(P0 + rb);
            cs.x += f0.x; cs.y += f0.y; cs.z += f0.z; cs.w += f0.w;
        }
        {
            float4 f1 = *(const float4*)(P1 + rb);
            float s1 = P1[c4];
            cs.x += f1.y; cs.y += f1.z; cs.z += f1.w; cs.w += s1;
        }
        if (ok2) {
            float4 f2 = *(const float4*)(P2 + rb);
            float sa = P2[c4], sb = P2[c5];
            cs.x += f2.z; cs.y += f2.w; cs.z += sa; cs.w += sb;
        }
        float4 k4 = *(const float4*)(k1 + rb);
        z.x = (k4.x - k1d0) - 2.f * cs.x;
        z.y = (k4.y - k1d0) - 2.f * cs.y;
        z.z = (k4.z - k1d0) - 2.f * cs.z;
        z.w = (k4.w - k1d0) - 2.f * cs.w;
        if (q4 == 11) { z.z = 0.f; z.w = 0.f; }   // jx=46,47 pad -> neutral
    }
    float s  = z.x + z.y + z.z + z.w;
    float sq = z.x * z.x + z.y * z.y + z.z * z.z + z.w * z.w;
    float muz = blkSum18(s, red) * (1.f / (float)C);
    float ez2 = blkSum18(sq, red) * (1.f / (float)C);
    float var = fmaxf(ez2 - muz * muz, 1e-12f);
    float inv_sd = rsqrtf(var);

    // LUT logit + exp; f4 store; accumulate Z
    float4 e4 = make_float4(0.f, 0.f, 0.f, 0.f);
    if (active) {
        float zl[4] = {z.x, z.y, z.z, z.w};
        float el[4];
#pragma unroll
        for (int L = 0; L < 4; L++) {
            float t = (zl[L] - muz) * inv_sd;
            float fi = fmaf(t, 256.f, 2048.f);
            fi = fminf(fmaxf(fi, 0.f), 4095.f);
            int i = (int)fi;
            float fr = fi - (float)i;
            float Ta = d_tanhT[i], Tb = d_tanhT[i + 1];
            el[L] = __expf(fmaf(fr, Tb - Ta, Ta));
        }
        e4 = make_float4(el[0], el[1], el[2], el[3]);
        if (q4 == 11) { e4.z = 0.f; e4.w = 0.f; }
    }
    float se = e4.x + e4.y + e4.z + e4.w;
    float Z = blkSum18(se, red);
    if (active)
        *(float4*)(d_CA + (size_t)p * CROW + rb) = e4;
    if (tid == 0) d_invZ[p] = 1.f / Z;
}

// ---------------- K6: Pm[y][x][u][v] = sum_dy invZ[row] * CA[(y+1-dy,x)][(u-dy)][v], float4 ----------------
__global__ void pm_kernel() {
    const int n4 = HW * HW * HW * (CP / 4);
    int idx = blockIdx.x * blockDim.x + threadIdx.x;
    if (idx >= n4) return;
    int q4 = idx % 12; int t = idx / 12;
    int u = t % HW;    t /= HW;
    int x = t % HW;    int y = t / HW;
    const float4* CA4 = (const float4*)d_CA;
    float4 s = make_float4(0.f, 0.f, 0.f, 0.f);
#pragma unroll
    for (int dy = 0; dy < 3; dy++) {
        int yy = y + 1 - dy, uu = u - dy;
        if ((unsigned)yy < (unsigned)HW && (unsigned)uu < (unsigned)JH) {
            int row = yy * HW + x;
            float iz = d_invZ[row];
            float4 g = CA4[(size_t)row * (CROW / 4) + uu * 12 + q4];
            s.x = fmaf(g.x, iz, s.x); s.y = fmaf(g.y, iz, s.y);
            s.z = fmaf(g.z, iz, s.z); s.w = fmaf(g.w, iz, s.w);
        }
    }
    if (q4 == 11) { s.z = 0.f; s.w = 0.f; }
    ((float4*)d_Pm)[idx] = s;
}

// ---------------- K7: CB[(y,x)][(u,v)] = sum_dx Pm[y][x+1-dx][u][v-dx], float4 ----------------
__global__ void cb_kernel() {
    const int n4 = PIX * PIX / 4;
    int idx = blockIdx.x * blockDim.x + threadIdx.x;
    if (idx >= n4) return;
    int q4 = idx % 12; int t = idx / 12;
    int u = t % HW;    t /= HW;
    int x = t % HW;    int y = t / HW;
    int v0 = q4 * 4;
    float4 o = make_float4(0.f, 0.f, 0.f, 0.f);
#pragma unroll
    for (int dx = 0; dx < 3; dx++) {
        int xx = x + 1 - dx;
        if ((unsigned)xx < (unsigned)HW) {
            int rowbase = ((y * HW + xx) * HW + u) * CP;
            float4 f = ((const float4*)d_Pm)[rowbase / 4 + q4];
            float sm1 = 0.f, sm2 = 0.f;
            if (v0 > 0) { sm1 = d_Pm[rowbase + v0 - 1]; sm2 = d_Pm[rowbase + v0 - 2]; }
            if (dx == 0) {
                o.x += f.x;  o.y += f.y;  o.z += f.z;  o.w += f.w;
            } else if (dx == 1) {
                o.x += sm1;  o.y += f.x;  o.z += f.y;  o.w += f.z;
            } else {
                o.x += sm2;  o.y += sm1;  o.z += f.x;  o.w += f.y;
            }
        }
    }
    ((float4*)d_CB)[((size_t)(y * HW + x) * 576) + u * 12 + q4] = o;
}

// ---------------- K8: acl partials = CB @ bg; 128-row tile, 8x4 micro, packed-B smem ----------------
// dynamic smem: As[128*66] (33792B) + Bpair[32*64] ull (16384B) = 50176 B
__global__ void gemmCB_kernel(int b) {
    extern __shared__ float sm[];
    float* Acb = sm;                                        // [m][k], stride 66
    unsigned long long* Bp = (unsigned long long*)(sm + 128 * 66);  // [kp][n]
    int ks = blockIdx.y;
    int mt = blockIdx.x * 128;
    const float* bgp = d_bg + (size_t)b * PIX * D;
    int tid = threadIdx.x;
    int ty = tid >> 4, tx = tid & 15;
    unsigned long long acc[8][4] = {};
    int kbase = ks * KSEG;
    for (int kt = 0; kt < KSEG; kt += 64) {
        int k0 = kbase + kt;
        for (int i = tid; i < 128 * 32; i += 256) {
            int r = i >> 5, c2 = i & 31;
            *(unsigned long long*)&Acb[r * 66 + c2 * 2] =
                *(const unsigned long long*)&d_CB[(size_t)(mt + r) * PIX + k0 + c2 * 2];
        }
        for (int i = tid; i < 32 * 64; i += 256) {
            int kp = i >> 6, n = i & 63;
            Bp[kp * 64 + n] = pack2(bgp[(k0 + 2 * kp) * D + n],
                                    bgp[(k0 + 2 * kp + 1) * D + n]);
        }
        __syncthreads();
#pragma unroll 8
        for (int kp = 0; kp < 32; kp++) {
            int k = kp * 2;
            unsigned long long a2[8], b2[4];
#pragma unroll
            for (int i = 0; i < 8; i++)
                a2[i] = *(const unsigned long long*)&Acb[(ty + 16 * i) * 66 + k];
#pragma unroll
            for (int j = 0; j < 4; j++)
                b2[j] = Bp[kp * 64 + tx + 16 * j];
#pragma unroll
            for (int i = 0; i < 8; i++)
#pragma unroll
                for (int j = 0; j < 4; j++) ffma2(acc[i][j], a2[i], b2[j]);
        }
        __syncthreads();
    }
    float* outp = d_aclp[ks];
#pragma unroll
    for (int i = 0; i < 8; i++)
#pragma unroll
        for (int j = 0; j < 4; j++)
            outp[(mt + ty + 16 * i) * D + tx + 16 * j] = pairsum(acc[i][j]);
}

// ---------------- K9: ACL + concat + W2 GEMM + ELU ----------------
__global__ void final_kernel(const float* __restrict__ g_in,
                             const float* __restrict__ mask,
                             const float* __restrict__ W2,
                             const float* __restrict__ b2,
                             float* __restrict__ out, int b) {
    __shared__ float w2s[128 * 64];
    __shared__ float cats[4][128];
    int tid = threadIdx.x;
    int g = tid >> 6, dch = tid & 63;
    int pl  = blockIdx.x * 4 + g;
    int pix = b * PIX + pl;
    for (int i = tid; i < 128 * 64; i += 256) w2s[i] = W2[i];

    float gv = g_in[pix * D + dch];
    float m  = mask[pix];
    float a  = 0.f;
#pragma unroll
    for (int s = 0; s < NSPLIT; s++) a += d_aclp[s][pl * D + dch];
    float ACL = d_bg[pix * D + dch] + a * (1.f / 9.f) * (1.f - m);
    cats[g][dch]      = gv;
    cats[g][64 + dch] = ACL;
    __syncthreads();

    float acc = b2[dch];
#pragma unroll 16
    for (int k = 0; k < 128; k++) acc += cats[g][k] * w2s[k * 64 + dch];
    out[pix * D + dch] = acc > 0.f ? acc : expm1f(acc);
}

// ---------------- launch ----------------
extern "C" void kernel_launch(void* const* d_in, const int* in_sizes, int n_in,
                              void* d_out, int out_size) {
    const float* g_in = (const float*)d_in[0];
    const float* mask = (const float*)d_in[1];
    const float* W2   = (const float*)d_in[2];
    const float* b2   = (const float*)d_in[3];
    float* out = (float*)d_out;

    cudaFuncSetAttribute(gemmCB_kernel,
                         cudaFuncAttributeMaxDynamicSharedMemorySize, 50176);

    table_kernel<<<17, 256>>>();
    prep_kernel<<<B * PIX / 4, 256>>>(g_in, mask);
    box_kernel<<<(B * C + 255) / 256, 256>>>();

    for (int b = 0; b < B; b++) {
        gemmG_kernel<<<dim3(PIX / 64, PIX / 64), 256>>>(g_in, mask, b);
        hbuild_kernel<<<(HW * HW * JH * (HW / 4) + 255) / 256, 256>>>();
        row_kernel<<<PIX, 576>>>(b);
        pm_kernel<<<(HW * HW * HW * (CP / 4) + 255) / 256, 256>>>();
        cb_kernel<<<(PIX * PIX / 4 + 255) / 256, 256>>>();
        gemmCB_kernel<<<dim3(PIX / 128, NSPLIT), 256, 50176>>>(b);
        final_kernel<<<PIX / 4, 256>>>(g_in, mask, W2, b2, out, b);
    }
}

// round 16
// speedup vs baseline: 1.9839x; 1.0480x over previous
#include <cuda_runtime.h>
#include <math.h>

#define B 4
#define HW 48
#define PIX 2304        // 48*48
#define D 64
#define JH 46
#define C 2116          // 46*46
#define CP 48           // padded inner dim
#define CROW (JH*CP)    // 2208, padded row length
#define NSPLIT 18
#define KSEG (PIX/NSPLIT)   // 128

// ---------------- scratch (device globals; per-batch reuse, ~118MB) ----------------
__device__ float d_bg[B*PIX*D];
__device__ float d_nbg[B*PIX];
__device__ float d_k1d[B*CROW];           // PADDED [jy][48] 3x3 valid box sum of nbg
__device__ float d_G[PIX*PIX];            // gram, one batch (21.2MB)
__device__ float d_Hh[HW*HW*JH*HW];       // y-diag sum of G (20.3MB)
__device__ float d_CA[PIX*CROW];          // UNSCALED exp weights, padded rows (20.3MB)
__device__ float d_invZ[PIX];             // per-row softmax 1/Z
__device__ float d_Pm[HW*HW*HW*CP];       // y-diag sum of scaled CA (21.2MB)
__device__ float d_CB[PIX*PIX];           // diag box sum of CA (21.2MB)
__device__ float d_aclp[NSPLIT][PIX*D];   // 10.6MB
__device__ float d_tanhT[4097];           // logit LUT: -50*tanh(t)-50, t in [-8,8]

// ---------------- f32x2 packed FMA ----------------
__device__ __forceinline__ void ffma2(unsigned long long& d,
                                      unsigned long long a,
                                      unsigned long long b) {
    asm("fma.rn.f32x2 %0, %1, %2, %3;" : "=l"(d) : "l"(a), "l"(b), "l"(d));
}
__device__ __forceinline__ unsigned long long pack2(float lo, float hi) {
    unsigned long long r;
    asm("mov.b64 %0, {%1, %2};" : "=l"(r) : "f"(lo), "f"(hi));
    return r;
}
__device__ __forceinline__ float pairsum(unsigned long long p) {
    float lo = __uint_as_float((unsigned)(p & 0xffffffffull));
    float hi = __uint_as_float((unsigned)(p >> 32));
    return lo + hi;
}

// ---------------- block reductions (256 threads, 8 warps) ----------------
__device__ __forceinline__ float blkSum(float v, volatile float* sh) {
    for (int o = 16; o; o >>= 1) v += __shfl_down_sync(0xffffffffu, v, o);
    int w = threadIdx.x >> 5;
    if ((threadIdx.x & 31) == 0) sh[w] = v;
    __syncthreads();
    if (threadIdx.x == 0) {
        float s = 0.f;
        for (int i = 0; i < 8; i++) s += sh[i];
        sh[0] = s;
    }
    __syncthreads();
    float r = sh[0];
    __syncthreads();
    return r;
}

// paired reduction: sum two values in one barrier round
__device__ __forceinline__ float2 blkSum2(float a, float b, volatile float2* sh) {
    for (int o = 16; o; o >>= 1) {
        a += __shfl_down_sync(0xffffffffu, a, o);
        b += __shfl_down_sync(0xffffffffu, b, o);
    }
    int w = threadIdx.x >> 5;
    if ((threadIdx.x & 31) == 0) { sh[w].x = a; sh[w].y = b; }
    __syncthreads();
    if (threadIdx.x == 0) {
        float sa = 0.f, sb = 0.f;
        for (int i = 0; i < 8; i++) { sa += sh[i].x; sb += sh[i].y; }
        sh[0].x = sa; sh[0].y = sb;
    }
    __syncthreads();
    float2 r = make_float2(sh[0].x, sh[0].y);
    __syncthreads();
    return r;
}

// ---------------- K0: logit LUT ----------------
__global__ void table_kernel() {
    int i = blockIdx.x * 256 + threadIdx.x;
    if (i < 4097) {
        float t = -8.f + i * (1.f / 256.f);
        d_tanhT[i] = -50.f * tanhf(t) - 50.f;
    }
}

// ---------------- K1: bg + masked pixel norm (all batches) ----------------
__global__ void prep_kernel(const float* __restrict__ g_in,
                            const float* __restrict__ mask) {
    int pix = blockIdx.x * 4 + (threadIdx.x >> 6);
    int ch  = threadIdx.x & 63;
    float g = g_in[pix * D + ch];
    float m = mask[pix];
    float bgv = g * m;
    d_bg[pix * D + ch] = bgv;
    float nb = bgv * bgv;
    for (int o = 16; o; o >>= 1)
        nb += __shfl_down_sync(0xffffffffu, nb, o);
    __shared__ float snb[8];
    int w = threadIdx.x >> 5;
    if ((threadIdx.x & 31) == 0) snb[w] = nb;
    __syncthreads();
    if (ch == 0)
        d_nbg[pix] = snb[w] + snb[w + 1];
}

// ---------------- K2: k1d valid box sum, PADDED rows (all batches) ----------------
__global__ void box_kernel() {
    int idx = blockIdx.x * blockDim.x + threadIdx.x;
    if (idx >= B * C) return;
    int b = idx / C, j = idx % C;
    int jy = j / JH, jx = j % JH;
    float s2 = 0.f;
    for (int dy = 0; dy < 3; dy++)
        for (int dx = 0; dx < 3; dx++)
            s2 += d_nbg[b * PIX + (jy + dy) * HW + (jx + dx)];
    d_k1d[b * CROW + jy * CP + jx] = s2;    // pad lanes stay 0
}

// ---------------- K3: G via SYMMETRIC gram, triangular 64x64 (measured 22.7us) ----------------
__global__ void gemmG_kernel(const float* __restrict__ g_in,
                             const float* __restrict__ mask, int b) {
    int ptile = blockIdx.y, qtile = blockIdx.x;
    if (ptile > qtile) return;
    __shared__ __align__(16) float As[64 * 66];
    __shared__ __align__(16) float Bs[64 * 66];
    __shared__ float mp[64], mq[64];
    int pt = ptile * 64, qt = qtile * 64;
    const float* Ap = g_in + (size_t)b * PIX * D;
    int tid = threadIdx.x;
    for (int i = tid; i < 4096; i += 256) {
        int r = i >> 6, c = i & 63;
        As[r * 66 + c] = Ap[(pt + r) * D + c];
        Bs[r * 66 + c] = Ap[(qt + r) * D + c];
    }
    if (tid < 64)       mp[tid]      = mask[b * PIX + pt + tid];
    else if (tid < 128) mq[tid - 64] = mask[b * PIX + qt + tid - 64];
    __syncthreads();
    int ty = tid >> 4, tx = tid & 15;
    unsigned long long acc[4][4] = {};
#pragma unroll
    for (int kp = 0; kp < 32; kp++) {
        int k = kp * 2;
        unsigned long long a2[4], b2[4];
#pragma unroll
        for (int i = 0; i < 4; i++) {
            a2[i] = *(const unsigned long long*)&As[(ty + 16 * i) * 66 + k];
            b2[i] = *(const unsigned long long*)&Bs[(tx + 16 * i) * 66 + k];
        }
#pragma unroll
        for (int i = 0; i < 4; i++)
#pragma unroll
            for (int j = 0; j < 4; j++) ffma2(acc[i][j], a2[i], b2[j]);
    }
    float v[4][4];
#pragma unroll
    for (int i = 0; i < 4; i++)
#pragma unroll
        for (int j = 0; j < 4; j++) {
            v[i][j] = pairsum(acc[i][j]);
            d_G[(size_t)(pt + ty + 16 * i) * PIX + qt + tx + 16 * j] =
                v[i][j] * mq[tx + 16 * j];
        }
    if (ptile == qtile) return;
    __syncthreads();
#pragma unroll
    for (int i = 0; i < 4; i++)
#pragma unroll
        for (int j = 0; j < 4; j++)
            As[(tx + 16 * j) * 66 + (ty + 16 * i)] = v[i][j];
    __syncthreads();
    for (int i = 0; i < 16; i++) {
        int idx = i * 256 + tid;
        int c = idx >> 6, r = idx & 63;
        d_G[(size_t)(qt + c) * PIX + pt + r] = As[c * 66 + r] * mp[r];
    }
}

// ---------------- K4: Hh[y][px][jy][qx] = sum_dy G[(y+dy-1,px)][(jy+dy)*48+qx], float4 ----------------
__global__ void hbuild_kernel() {
    const int n4 = HW * HW * JH * (HW / 4);
    int idx = blockIdx.x * blockDim.x + threadIdx.x;
    if (idx >= n4) return;
    int q4 = idx % 12; int t = idx / 12;
    int jy = t % JH;   t /= JH;
    int px = t % HW;   int y = t / HW;
    const float4* G4 = (const float4*)d_G;
    float4 s = make_float4(0.f, 0.f, 0.f, 0.f);
#pragma unroll
    for (int dy = 0; dy < 3; dy++) {
        int yy = y + dy - 1;
        if ((unsigned)yy < (unsigned)HW) {
            float4 g = G4[(size_t)(yy * HW + px) * (PIX / 4) + (jy + dy) * 12 + q4];
            s.x += g.x; s.y += g.y; s.z += g.z; s.w += g.w;
        }
    }
    ((float4*)d_Hh)[idx] = s;
}

// ---------------- K5: fused CS row + stats + LUT softmax; 256 thr, 3 f4 units, z in regs ----------------
__global__ void row_kernel(int b) {
    __shared__ float2 red2[8];
    __shared__ float red[8];
    int p = blockIdx.x;
    int y = p / HW, x = p % HW;
    int tid = threadIdx.x;
    const float* k1 = d_k1d + b * CROW;
    float k1d0 = k1[0];
    bool ok0 = (x - 1) >= 0, ok2 = (x + 1) < HW;
    const float* P0 = d_Hh + (size_t)(y * HW + (x - 1)) * JH * HW;
    const float* P1 = d_Hh + (size_t)(y * HW + x) * JH * HW;
    const float* P2 = d_Hh + (size_t)(y * HW + (x + 1)) * JH * HW;

    // pass A: z = (k1d - k1d0) - 2*cs; z stays in registers (3 f4 units/thread)
    float4 zreg[3];
    float s = 0.f, sq = 0.f;
#pragma unroll
    for (int it = 0; it < 3; it++) {
        int u = tid + it * 256;
        if (u >= JH * 12) break;
        int jy = u / 12, q4 = u - jy * 12;
        int v0 = q4 * 4;
        int rb = jy * CP + v0;
        int c4 = jy * CP + ((v0 + 4 < 48) ? v0 + 4 : 47);
        int c5 = jy * CP + ((v0 + 5 < 48) ? v0 + 5 : 47);
        float4 cs = make_float4(0.f, 0.f, 0.f, 0.f);
        if (ok0) {
            float4 f0 = *(const float4*)(P0 + rb);
            cs.x += f0.x; cs.y += f0.y; cs.z += f0.z; cs.w += f0.w;
        }
        {
            float4 f1 = *(const float4*)(P1 + rb);
            float s1 = P1[c4];
            cs.x += f1.y; cs.y += f1.z; cs.z += f1.w; cs.w += s1;
        }
        if (ok2) {
            float4 f2 = *(const float4*)(P2 + rb);
            float sa = P2[c4], sb = P2[c5];
            cs.x += f2.z; cs.y += f2.w; cs.z += sa; cs.w += sb;
        }
        float4 k4 = *(const float4*)(k1 + rb);
        float4 z;
        z.x = (k4.x - k1d0) - 2.f * cs.x;
        z.y = (k4.y - k1d0) - 2.f * cs.y;
        z.z = (k4.z - k1d0) - 2.f * cs.z;
        z.w = (k4.w - k1d0) - 2.f * cs.w;
        if (q4 == 11) { z.z = 0.f; z.w = 0.f; }   // jx=46,47 pad -> neutral
        zreg[it] = z;
        s += z.x + z.y + z.z + z.w;
        sq = fmaf(z.x, z.x, sq); sq = fmaf(z.y, z.y, sq);
        sq = fmaf(z.z, z.z, sq); sq = fmaf(z.w, z.w, sq);
    }
    float2 mv = blkSum2(s, sq, red2);
    float muz = mv.x * (1.f / (float)C);
    float ez2 = mv.y * (1.f / (float)C);
    float var = fmaxf(ez2 - muz * muz, 1e-12f);
    float inv_sd = rsqrtf(var);

    // pass B: LUT logit + exp from registers, f4 stores to CA; accumulate Z
    float se = 0.f;
    float* cap = d_CA + (size_t)p * CROW;
#pragma unroll
    for (int it = 0; it < 3; it++) {
        int u = tid + it * 256;
        if (u >= JH * 12) break;
        int jy = u / 12, q4 = u - jy * 12;
        int rb = jy * CP + q4 * 4;
        float4 z4 = zreg[it];
        float zl[4] = {z4.x, z4.y, z4.z, z4.w};
        float el[4];
#pragma unroll
        for (int L = 0; L < 4; L++) {
            float t = (zl[L] - muz) * inv_sd;
            float fi = fmaf(t, 256.f, 2048.f);
            fi = fminf(fmaxf(fi, 0.f), 4095.f);
            int i = (int)fi;
            float fr = fi - (float)i;
            float Ta = d_tanhT[i], Tb = d_tanhT[i + 1];
            el[L] = __expf(fmaf(fr, Tb - Ta, Ta));
        }
        float4 e4 = make_float4(el[0], el[1], el[2], el[3]);
        if (q4 == 11) { e4.z = 0.f; e4.w = 0.f; }
        se += e4.x + e4.y + e4.z + e4.w;
        *(float4*)(cap + rb) = e4;
    }
    float Z = blkSum(se, red);
    if (tid == 0) d_invZ[p] = 1.f / Z;
}

// ---------------- K6: Pm[y][x][u][v] = sum_dy invZ[row] * CA[(y+1-dy,x)][(u-dy)][v], float4 ----------------
__global__ void pm_kernel() {
    const int n4 = HW * HW * HW * (CP / 4);
    int idx = blockIdx.x * blockDim.x + threadIdx.x;
    if (idx >= n4) return;
    int q4 = idx % 12; int t = idx / 12;
    int u = t % HW;    t /= HW;
    int x = t % HW;    int y = t / HW;
    const float4* CA4 = (const float4*)d_CA;
    float4 s = make_float4(0.f, 0.f, 0.f, 0.f);
#pragma unroll
    for (int dy = 0; dy < 3; dy++) {
        int yy = y + 1 - dy, uu = u - dy;
        if ((unsigned)yy < (unsigned)HW && (unsigned)uu < (unsigned)JH) {
            int row = yy * HW + x;
            float iz = d_invZ[row];
            float4 g = CA4[(size_t)row * (CROW / 4) + uu * 12 + q4];
            s.x = fmaf(g.x, iz, s.x); s.y = fmaf(g.y, iz, s.y);
            s.z = fmaf(g.z, iz, s.z); s.w = fmaf(g.w, iz, s.w);
        }
    }
    if (q4 == 11) { s.z = 0.f; s.w = 0.f; }
    ((float4*)d_Pm)[idx] = s;
}

// ---------------- K7: CB[(y,x)][(u,v)] = sum_dx Pm[y][x+1-dx][u][v-dx], float4 ----------------
__global__ void cb_kernel() {
    const int n4 = PIX * PIX / 4;
    int idx = blockIdx.x * blockDim.x + threadIdx.x;
    if (idx >= n4) return;
    int q4 = idx % 12; int t = idx / 12;
    int u = t % HW;    t /= HW;
    int x = t % HW;    int y = t / HW;
    int v0 = q4 * 4;
    float4 o = make_float4(0.f, 0.f, 0.f, 0.f);
#pragma unroll
    for (int dx = 0; dx < 3; dx++) {
        int xx = x + 1 - dx;
        if ((unsigned)xx < (unsigned)HW) {
            int rowbase = ((y * HW + xx) * HW + u) * CP;
            float4 f = ((const float4*)d_Pm)[rowbase / 4 + q4];
            float sm1 = 0.f, sm2 = 0.f;
            if (v0 > 0) { sm1 = d_Pm[rowbase + v0 - 1]; sm2 = d_Pm[rowbase + v0 - 2]; }
            if (dx == 0) {
                o.x += f.x;  o.y += f.y;  o.z += f.z;  o.w += f.w;
            } else if (dx == 1) {
                o.x += sm1;  o.y += f.x;  o.z += f.y;  o.w += f.z;
            } else {
                o.x += sm2;  o.y += sm1;  o.z += f.x;  o.w += f.y;
            }
        }
    }
    ((float4*)d_CB)[((size_t)(y * HW + x) * 576) + u * 12 + q4] = o;
}

// ---------------- K8: acl partials = CB @ bg; 128-row tile, 8x4 micro, packed-B smem ----------------
// dynamic smem: As[128*66] (33792B) + Bpair[32*64] ull (16384B) = 50176 B
__global__ void gemmCB_kernel(int b) {
    extern __shared__ float sm[];
    float* Acb = sm;                                        // [m][k], stride 66
    unsigned long long* Bp = (unsigned long long*)(sm + 128 * 66);  // [kp][n]
    int ks = blockIdx.y;
    int mt = blockIdx.x * 128;
    const float* bgp = d_bg + (size_t)b * PIX * D;
    int tid = threadIdx.x;
    int ty = tid >> 4, tx = tid & 15;
    unsigned long long acc[8][4] = {};
    int kbase = ks * KSEG;
    for (int kt = 0; kt < KSEG; kt += 64) {
        int k0 = kbase + kt;
        for (int i = tid; i < 128 * 32; i += 256) {
            int r = i >> 5, c2 = i & 31;
            *(unsigned long long*)&Acb[r * 66 + c2 * 2] =
                *(const unsigned long long*)&d_CB[(size_t)(mt + r) * PIX + k0 + c2 * 2];
        }
        for (int i = tid; i < 32 * 64; i += 256) {
            int kp = i >> 6, n = i & 63;
            Bp[kp * 64 + n] = pack2(bgp[(k0 + 2 * kp) * D + n],
                                    bgp[(k0 + 2 * kp + 1) * D + n]);
        }
        __syncthreads();
#pragma unroll 8
        for (int kp = 0; kp < 32; kp++) {
            int k = kp * 2;
            unsigned long long a2[8], b2[4];
#pragma unroll
            for (int i = 0; i < 8; i++)
                a2[i] = *(const unsigned long long*)&Acb[(ty + 16 * i) * 66 + k];
#pragma unroll
            for (int j = 0; j < 4; j++)
                b2[j] = Bp[kp * 64 + tx + 16 * j];
#pragma unroll
            for (int i = 0; i < 8; i++)
#pragma unroll
                for (int j = 0; j < 4; j++) ffma2(acc[i][j], a2[i], b2[j]);
        }
        __syncthreads();
    }
    float* outp = d_aclp[ks];
#pragma unroll
    for (int i = 0; i < 8; i++)
#pragma unroll
        for (int j = 0; j < 4; j++)
            outp[(mt + ty + 16 * i) * D + tx + 16 * j] = pairsum(acc[i][j]);
}

// ---------------- K9: ACL + concat + W2 GEMM + ELU ----------------
__global__ void final_kernel(const float* __restrict__ g_in,
                             const float* __restrict__ mask,
                             const float* __restrict__ W2,
                             const float* __restrict__ b2,
                             float* __restrict__ out, int b) {
    __shared__ float w2s[128 * 64];
    __shared__ float cats[4][128];
    int tid = threadIdx.x;
    int g = tid >> 6, dch = tid & 63;
    int pl  = blockIdx.x * 4 + g;
    int pix = b * PIX + pl;
    for (int i = tid; i < 128 * 64; i += 256) w2s[i] = W2[i];

    float gv = g_in[pix * D + dch];
    float m  = mask[pix];
    float a  = 0.f;
#pragma unroll
    for (int s = 0; s < NSPLIT; s++) a += d_aclp[s][pl * D + dch];
    float ACL = d_bg[pix * D + dch] + a * (1.f / 9.f) * (1.f - m);
    cats[g][dch]      = gv;
    cats[g][64 + dch] = ACL;
    __syncthreads();

    float acc = b2[dch];
#pragma unroll 16
    for (int k = 0; k < 128; k++) acc += cats[g][k] * w2s[k * 64 + dch];
    out[pix * D + dch] = acc > 0.f ? acc : expm1f(acc);
}

// ---------------- launch ----------------
extern "C" void kernel_launch(void* const* d_in, const int* in_sizes, int n_in,
                              void* d_out, int out_size) {
    const float* g_in = (const float*)d_in[0];
    const float* mask = (const float*)d_in[1];
    const float* W2   = (const float*)d_in[2];
    const float* b2   = (const float*)d_in[3];
    float* out = (float*)d_out;

    cudaFuncSetAttribute(gemmCB_kernel,
                         cudaFuncAttributeMaxDynamicSharedMemorySize, 50176);

    table_kernel<<<17, 256>>>();
    prep_kernel<<<B * PIX / 4, 256>>>(g_in, mask);
    box_kernel<<<(B * C + 255) / 256, 256>>>();

    for (int b = 0; b < B; b++) {
        gemmG_kernel<<<dim3(PIX / 64, PIX / 64), 256>>>(g_in, mask, b);
        hbuild_kernel<<<(HW * HW * JH * (HW / 4) + 255) / 256, 256>>>();
        row_kernel<<<PIX, 256>>>(b);
        pm_kernel<<<(HW * HW * HW * (CP / 4) + 255) / 256, 256>>>();
        cb_kernel<<<(PIX * PIX / 4 + 255) / 256, 256>>>();
        gemmCB_kernel<<<dim3(PIX / 128, NSPLIT), 256, 50176>>>(b);
        final_kernel<<<PIX / 4, 256>>>(g_in, mask, W2, b2, out, b);
    }
}